// round 4
// baseline (speedup 1.0000x reference)
#include <cuda_runtime.h>
#include <math.h>

#define NN 100000
#define KK 20
#define DD 96
#define HH 1024
#define CC 7
#define NCHUNK 32
#define NPER (NN / NCHUNK)   // 3125

// ---------------- scratch (static device globals; no allocations) ----------------
static __device__ float  d_protoN[CC * DD];
static __device__ int    d_preds[NN];
static __device__ float  d_maskf[NN];
static __device__ float  d_featH[(long long)NN * HH];   // 400 MB
static __device__ float  d_Qpart[NCHUNK * HH * CC];
static __device__ float  d_Qn[HH * CC];
static __device__ float  d_Gn[HH * HH];
static __device__ double d_Gd[HH * HH];
static __device__ float  d_wo[HH * CC];
static __device__ int    d_idx64flag;   // 1 if near_indices buffer is int64, 0 if int32

// ---------------- detect index dtype (int64 vs int32) ----------------
__global__ void detect_idx_kernel(const void* __restrict__ nidx) {
    // Interpret the first 1024 entries as int64 pairs (lo,hi int32). For genuine
    // little-endian int64 indices < 2^31, every hi word is 0. For int32 data,
    // the "hi" words are actual random indices in [0,100000) -> virtually never all 0.
    const int* p = (const int*)nidx;
    int allzero = 1;
    for (int k = 0; k < 1024; k++) {
        if (p[2 * k + 1] != 0) { allzero = 0; break; }
    }
    d_idx64flag = allzero;
}

// ---------------- tiny: normalize prototypes ----------------
__global__ void protoN_kernel(const float* __restrict__ proto) {
    int c = threadIdx.x;
    if (c < CC) {
        float s = 0.f;
        for (int k = 0; k < DD; k++) { float v = proto[c * DD + k]; s += v * v; }
        float nrm = sqrtf(s);
        nrm = fmaxf(nrm, 1e-12f);
        float inv = 1.f / nrm;
        for (int k = 0; k < DD; k++) d_protoN[c * DD + k] = proto[c * DD + k] * inv;
    }
}

// ---------------- per-point argmax over 7 prototype dots ----------------
__global__ __launch_bounds__(256) void preds_kernel(const float* __restrict__ feat) {
    __shared__ float sp[CC][DD];
    int tid = threadIdx.x;
    for (int i = tid; i < CC * DD; i += 256) sp[i / DD][i % DD] = d_protoN[i];
    __syncthreads();
    int n = blockIdx.x * 256 + tid;
    if (n >= NN) return;
    const float* f = feat + (long long)n * DD;
    float acc[CC];
#pragma unroll
    for (int c = 0; c < CC; c++) acc[c] = 0.f;
    for (int k = 0; k < DD; k++) {
        float fk = f[k];
#pragma unroll
        for (int c = 0; c < CC; c++) acc[c] += fk * sp[c][k];
    }
    float best = acc[0];
    int bi = 0;
#pragma unroll
    for (int c = 1; c < CC; c++) {
        if (acc[c] > best) { best = acc[c]; bi = c; }
    }
    d_preds[n] = bi;
}

// ---------------- KNN consistency + prior filters -> mask ----------------
__global__ __launch_bounds__(256) void mask_kernel(const float* __restrict__ coords,
                                                   const float* __restrict__ normz,
                                                   const void* __restrict__ nidx) {
    int n = blockIdx.x * 256 + threadIdx.x;
    if (n >= NN) return;
    int p = d_preds[n];
    int is64 = d_idx64flag;
    const long long* ni64 = (const long long*)nidx;
    const int*       ni32 = (const int*)nidx;
    int cnt = 0;
#pragma unroll
    for (int k = 0; k < KK; k++) {
        long long raw = is64 ? ni64[(long long)n * KK + k]
                             : (long long)ni32[(long long)n * KK + k];
        unsigned int idx = (unsigned int)raw;
        if (idx >= NN) idx = 0;   // safety clamp (should never trigger)
        cnt += (d_preds[idx] == p);
    }
    bool cmask = cnt > 16;  // cnt/20 > 0.8

    bool plane   = (p == 2) | (p == 3) | (p == 4);
    bool manmade = (p == 5);
    bool other   = (p == 0) | (p == 1) | (p == 6);
    float nz = normz[n];
    float z  = coords[(long long)n * 3 + 2];
    bool ground = plane && (nz > 0.9f) && (z < -10.0f);
    bool g = ground || other || manmade;
    bool m = (manmade && (nz < 0.1f)) || other || plane;
    d_maskf[n] = (cmask && g && m) ? 1.f : 0.f;
}

// ---------------- feat_h = relu(feat @ W) : [100000 x 96] @ [96 x 1024] ----------------
__global__ __launch_bounds__(256) void feath_kernel(const float* __restrict__ feat,
                                                    const float* __restrict__ w) {
    __shared__ __align__(16) float As[32][68];   // As[k][m] = feat[n0+m][k0+k]
    __shared__ __align__(16) float Bs[32][68];   // Bs[k][j] = w[k0+k][h0+j]
    int tid = threadIdx.x;
    int h0 = blockIdx.x * 64;
    int n0 = blockIdx.y * 64;
    int tx = tid & 15, ty = tid >> 4;
    float acc[4][4];
#pragma unroll
    for (int r = 0; r < 4; r++)
#pragma unroll
        for (int s = 0; s < 4; s++) acc[r][s] = 0.f;

    for (int k0 = 0; k0 < DD; k0 += 32) {
        for (int i = tid; i < 64 * 32; i += 256) {
            int k = i & 31, m = i >> 5;
            int n = n0 + m;
            As[k][m] = (n < NN) ? feat[(long long)n * DD + k0 + k] : 0.f;
        }
        for (int i = tid; i < 32 * 64; i += 256) {
            int k = i >> 6, m = i & 63;
            Bs[k][m] = w[(k0 + k) * HH + h0 + m];
        }
        __syncthreads();
#pragma unroll
        for (int k = 0; k < 32; k++) {
            float4 a = *reinterpret_cast<const float4*>(&As[k][ty << 2]);
            float4 b = *reinterpret_cast<const float4*>(&Bs[k][tx << 2]);
            acc[0][0] += a.x * b.x; acc[0][1] += a.x * b.y; acc[0][2] += a.x * b.z; acc[0][3] += a.x * b.w;
            acc[1][0] += a.y * b.x; acc[1][1] += a.y * b.y; acc[1][2] += a.y * b.z; acc[1][3] += a.y * b.w;
            acc[2][0] += a.z * b.x; acc[2][1] += a.z * b.y; acc[2][2] += a.z * b.z; acc[2][3] += a.z * b.w;
            acc[3][0] += a.w * b.x; acc[3][1] += a.w * b.y; acc[3][2] += a.w * b.z; acc[3][3] += a.w * b.w;
        }
        __syncthreads();
    }
#pragma unroll
    for (int r = 0; r < 4; r++) {
        int n = n0 + (ty << 2) + r;
        if (n < NN) {
#pragma unroll
            for (int s = 0; s < 4; s++)
                d_featH[(long long)n * HH + h0 + (tx << 2) + s] = fmaxf(acc[r][s], 0.f);
        }
    }
}

// ---------------- Gn = (mask*featH)^T @ featH + Gin : [1024 x 1024], K = 100000 ----------------
__global__ __launch_bounds__(256) void gram_kernel(const float* __restrict__ Gin) {
    __shared__ __align__(16) float As[32][68];   // As[k][m] = featH[n0+k][h10+m] * mask
    __shared__ __align__(16) float Bs[32][68];   // Bs[k][m] = featH[n0+k][h20+m]
    int tid = threadIdx.x;
    int h10 = blockIdx.y * 64, h20 = blockIdx.x * 64;
    int tx = tid & 15, ty = tid >> 4;
    float acc[4][4];
#pragma unroll
    for (int r = 0; r < 4; r++)
#pragma unroll
        for (int s = 0; s < 4; s++) acc[r][s] = 0.f;

    for (int n0 = 0; n0 < NN; n0 += 32) {
        for (int i = tid; i < 2048; i += 256) {
            int k = i >> 6, m = i & 63;
            int n = n0 + k;
            long long base = (long long)n * HH;
            float mv = d_maskf[n];
            As[k][m] = d_featH[base + h10 + m] * mv;
            Bs[k][m] = d_featH[base + h20 + m];
        }
        __syncthreads();
#pragma unroll
        for (int k = 0; k < 32; k++) {
            float4 a = *reinterpret_cast<const float4*>(&As[k][ty << 2]);
            float4 b = *reinterpret_cast<const float4*>(&Bs[k][tx << 2]);
            acc[0][0] += a.x * b.x; acc[0][1] += a.x * b.y; acc[0][2] += a.x * b.z; acc[0][3] += a.x * b.w;
            acc[1][0] += a.y * b.x; acc[1][1] += a.y * b.y; acc[1][2] += a.y * b.z; acc[1][3] += a.y * b.w;
            acc[2][0] += a.z * b.x; acc[2][1] += a.z * b.y; acc[2][2] += a.z * b.z; acc[2][3] += a.z * b.w;
            acc[3][0] += a.w * b.x; acc[3][1] += a.w * b.y; acc[3][2] += a.w * b.z; acc[3][3] += a.w * b.w;
        }
        __syncthreads();
    }
#pragma unroll
    for (int r = 0; r < 4; r++) {
        int row = h10 + (ty << 2) + r;
#pragma unroll
        for (int s = 0; s < 4; s++) {
            int col = h20 + (tx << 2) + s;
            d_Gn[row * HH + col] = acc[r][s] + Gin[row * HH + col];
        }
    }
}

// ---------------- Qn partials: per n-chunk class-wise column sums ----------------
__global__ __launch_bounds__(256) void qpart_kernel() {
    int h = blockIdx.x * 256 + threadIdx.x;
    int chunk = blockIdx.y;
    int nb = chunk * NPER;
    float a0 = 0, a1 = 0, a2 = 0, a3 = 0, a4 = 0, a5 = 0, a6 = 0;
    for (int t = 0; t < NPER; t++) {
        int n = nb + t;
        float mv = d_maskf[n];
        if (mv != 0.f) {   // uniform across block
            float v = d_featH[(long long)n * HH + h];
            int p = d_preds[n];
            a0 += (p == 0) ? v : 0.f;
            a1 += (p == 1) ? v : 0.f;
            a2 += (p == 2) ? v : 0.f;
            a3 += (p == 3) ? v : 0.f;
            a4 += (p == 4) ? v : 0.f;
            a5 += (p == 5) ? v : 0.f;
            a6 += (p == 6) ? v : 0.f;
        }
    }
    int o = (chunk * HH + h) * CC;
    d_Qpart[o + 0] = a0; d_Qpart[o + 1] = a1; d_Qpart[o + 2] = a2; d_Qpart[o + 3] = a3;
    d_Qpart[o + 4] = a4; d_Qpart[o + 5] = a5; d_Qpart[o + 6] = a6;
}

__global__ void qreduce_kernel(const float* __restrict__ Qin) {
    int idx = blockIdx.x * 256 + threadIdx.x;
    if (idx >= HH * CC) return;
    float s = Qin[idx];
    for (int ch = 0; ch < NCHUNK; ch++) s += d_Qpart[ch * HH * CC + idx];
    d_Qn[idx] = s;
}

// ---------------- convert to fp64 + ridge ----------------
__global__ void conv_kernel() {
    int idx = blockIdx.x * 256 + threadIdx.x;
    int i = idx >> 10, j = idx & 1023;
    d_Gd[idx] = (double)d_Gn[idx] + ((i == j) ? 100.0 : 0.0);
}

// ---------------- blocked fp64 Cholesky (lower), block = 64 ----------------
__global__ void chol_potf2(int kb) {
    int i = threadIdx.x;  // 64 threads
    int off = kb * 64;
    __shared__ double s[64][65];
    for (int j = 0; j < 64; j++) s[i][j] = d_Gd[(off + i) * HH + off + j];
    __syncthreads();
    for (int j = 0; j < 64; j++) {
        if (i == j) s[j][j] = sqrt(s[j][j]);
        __syncthreads();
        if (i > j) s[i][j] /= s[j][j];
        __syncthreads();
        if (i > j) {
            double lij = s[i][j];
            for (int k = j + 1; k <= i; k++) s[i][k] -= lij * s[k][j];
        }
        __syncthreads();
    }
    for (int j = 0; j <= i; j++) d_Gd[(off + i) * HH + off + j] = s[i][j];
}

__global__ __launch_bounds__(128) void chol_trsm(int kb) {
    int off = kb * 64;
    int base = off + 64;
    __shared__ double L[64][65];
    for (int i = threadIdx.x; i < 64 * 64; i += 128)
        L[i >> 6][i & 63] = d_Gd[(off + (i >> 6)) * HH + off + (i & 63)];
    __syncthreads();
    int r = base + blockIdx.x * 128 + threadIdx.x;
    if (r >= HH) return;
    double x[64];
    double* a = &d_Gd[r * HH + off];
    for (int j = 0; j < 64; j++) {
        double v = a[j];
        for (int t = 0; t < j; t++) v -= x[t] * L[j][t];
        x[j] = v / L[j][j];
    }
    for (int j = 0; j < 64; j++) a[j] = x[j];
}

__global__ __launch_bounds__(256) void chol_syrk(int kb) {
    int off = kb * 64;
    int base = off + 64;
    int i0 = base + blockIdx.y * 32;
    int j0 = base + blockIdx.x * 32;
    if (j0 > i0) return;  // uniform per block
    __shared__ double Li[32][65];
    __shared__ double Lj[32][65];
    int tid = threadIdx.x;
    for (int i = tid; i < 32 * 64; i += 256) {
        int ii = i >> 6, t = i & 63;
        Li[ii][t] = d_Gd[(i0 + ii) * HH + off + t];
        Lj[ii][t] = d_Gd[(j0 + ii) * HH + off + t];
    }
    __syncthreads();
    int tx = tid & 31, ty = tid >> 5;   // ty 0..7
    double acc[4] = {0, 0, 0, 0};
    for (int t = 0; t < 64; t++) {
        double bj = Lj[tx][t];
#pragma unroll
        for (int r = 0; r < 4; r++) acc[r] += Li[(ty << 2) + r][t] * bj;
    }
#pragma unroll
    for (int r = 0; r < 4; r++) {
        int i = i0 + (ty << 2) + r;
        int j = j0 + tx;
        if (j <= i) d_Gd[i * HH + j] -= acc[r];
    }
}

// ---------------- triangular solves: L y = Qn ; L^T wo = y (7 RHS) ----------------
__global__ __launch_bounds__(1024) void chol_solve() {
    int i = threadIdx.x;  // 0..1023
    __shared__ double shy[64][CC];
    double y[CC];
#pragma unroll
    for (int c = 0; c < CC; c++) y[c] = (double)d_Qn[i * CC + c];
    // forward
    for (int jb = 0; jb < HH; jb += 64) {
        for (int j = jb; j < jb + 64; j++) {
            if (i == j) {
                double dgl = d_Gd[j * HH + j];
#pragma unroll
                for (int c = 0; c < CC; c++) { y[c] /= dgl; shy[j - jb][c] = y[c]; }
            }
            __syncthreads();
            if (i > j && i < jb + 64) {
                double lij = d_Gd[i * HH + j];
#pragma unroll
                for (int c = 0; c < CC; c++) y[c] -= lij * shy[j - jb][c];
            }
            __syncthreads();
        }
        if (i >= jb + 64) {
            for (int t = 0; t < 64; t++) {
                double lij = d_Gd[i * HH + jb + t];
#pragma unroll
                for (int c = 0; c < CC; c++) y[c] -= lij * shy[t][c];
            }
        }
        __syncthreads();
    }
    // backward (uses L^T => reads L[j][i], coalesced across i)
    for (int jb = HH - 64; jb >= 0; jb -= 64) {
        for (int j = jb + 63; j >= jb; j--) {
            if (i == j) {
                double dgl = d_Gd[j * HH + j];
#pragma unroll
                for (int c = 0; c < CC; c++) { y[c] /= dgl; shy[j - jb][c] = y[c]; }
            }
            __syncthreads();
            if (i >= jb && i < j) {
                double lji = d_Gd[j * HH + i];
#pragma unroll
                for (int c = 0; c < CC; c++) y[c] -= lji * shy[j - jb][c];
            }
            __syncthreads();
        }
        if (i < jb) {
            for (int t = 0; t < 64; t++) {
                double lji = d_Gd[(jb + t) * HH + i];
#pragma unroll
                for (int c = 0; c < CC; c++) y[c] -= lji * shy[t][c];
            }
        }
        __syncthreads();
    }
#pragma unroll
    for (int c = 0; c < CC; c++) d_wo[i * CC + c] = (float)y[c];
}

// ---------------- pred_domain = featH @ wo : warp per row ----------------
__global__ __launch_bounds__(256) void final_kernel(float* __restrict__ out) {
    __shared__ float sw[HH * CC];  // 28 KB
    int tid = threadIdx.x;
    for (int i = tid; i < HH * CC; i += 256) sw[i] = d_wo[i];
    __syncthreads();
    int warp = tid >> 5, lane = tid & 31;
    int n = blockIdx.x * 8 + warp;
    if (n >= NN) return;
    const float* a = &d_featH[(long long)n * HH];
    float acc[CC];
#pragma unroll
    for (int c = 0; c < CC; c++) acc[c] = 0.f;
    for (int h = lane; h < HH; h += 32) {
        float v = a[h];
#pragma unroll
        for (int c = 0; c < CC; c++) acc[c] += v * sw[h * CC + c];
    }
#pragma unroll
    for (int c = 0; c < CC; c++) {
#pragma unroll
        for (int off = 16; off > 0; off >>= 1)
            acc[c] += __shfl_xor_sync(0xffffffffu, acc[c], off);
    }
    if (lane == 0) {
#pragma unroll
        for (int c = 0; c < CC; c++) out[(long long)n * CC + c] = acc[c];
    }
}

// ---------------- launcher ----------------
extern "C" void kernel_launch(void* const* d_in, const int* in_sizes, int n_in,
                              void* d_out, int out_size) {
    const float* feat   = (const float*)d_in[0];
    const float* proto  = (const float*)d_in[1];
    const float* wrand  = (const float*)d_in[2];
    const float* Qin    = (const float*)d_in[3];
    const float* Gin    = (const float*)d_in[4];
    const float* coords = (const float*)d_in[5];
    const float* normz  = (const float*)d_in[6];
    const void*  nidx   = (const void*)d_in[7];
    float* out = (float*)d_out;

    detect_idx_kernel<<<1, 1>>>(nidx);
    protoN_kernel<<<1, 32>>>(proto);
    preds_kernel<<<(NN + 255) / 256, 256>>>(feat);
    mask_kernel<<<(NN + 255) / 256, 256>>>(coords, normz, nidx);
    feath_kernel<<<dim3(HH / 64, (NN + 63) / 64), 256>>>(feat, wrand);
    gram_kernel<<<dim3(HH / 64, HH / 64), 256>>>(Gin);
    qpart_kernel<<<dim3(HH / 256, NCHUNK), 256>>>();
    qreduce_kernel<<<(HH * CC + 255) / 256, 256>>>(Qin);
    conv_kernel<<<(HH * HH) / 256, 256>>>();

    for (int kb = 0; kb < HH / 64; kb++) {
        chol_potf2<<<1, 64>>>(kb);
        int rows = HH - (kb * 64 + 64);
        if (rows > 0) {
            chol_trsm<<<(rows + 127) / 128, 128>>>(kb);
            int nt = (rows + 31) / 32;
            chol_syrk<<<dim3(nt, nt), 256>>>(kb);
        }
    }
    chol_solve<<<1, 1024>>>();
    final_kernel<<<(NN + 7) / 8, 256>>>(out);
}

// round 5
// speedup vs baseline: 2.0959x; 2.0959x over previous
#include <cuda_runtime.h>
#include <math.h>

#define NN 100000
#define KK 20
#define DD 96
#define HH 1024
#define CC 7
#define NCHUNK 32
#define NPER (NN / NCHUNK)   // 3125
#define GSPLIT 4
#define NSPL (NN / GSPLIT)   // 25000
#define GITER (NSPL / 8)     // 3125
#define NTRI 36              // 8x8 lower-triangle block count

// ---------------- scratch (static device globals; no allocations) ----------------
static __device__ float  d_protoN[CC * DD];
static __device__ int    d_preds[NN];
static __device__ float  d_maskf[NN];
static __device__ float  d_featH[(long long)NN * HH];   // 400 MB
static __device__ float  d_Spart[GSPLIT * NTRI * 128 * 128];  // 9.4 MB split-K partials
static __device__ float  d_Qpart[NCHUNK * HH * CC];
static __device__ float  d_Qn[HH * CC];
static __device__ float  d_Gn[HH * HH];
static __device__ double d_Gd[HH * HH];
static __device__ double d_dinv[HH];
static __device__ float  d_wo[HH * CC];
static __device__ int    d_idx64flag;

// ---------------- f32x2 helpers ----------------
__device__ __forceinline__ unsigned long long ffma2(unsigned long long a,
                                                    unsigned long long b,
                                                    unsigned long long c) {
    unsigned long long d;
    asm("fma.rn.f32x2 %0, %1, %2, %3;" : "=l"(d) : "l"(a), "l"(b), "l"(c));
    return d;
}
__device__ __forceinline__ unsigned long long dup2(float x) {
    unsigned long long d;
    asm("mov.b64 %0, {%1, %1};" : "=l"(d) : "f"(x));
    return d;
}
__device__ __forceinline__ float2 up2(unsigned long long v) {
    float2 r;
    asm("mov.b64 {%0, %1}, %2;" : "=f"(r.x), "=f"(r.y) : "l"(v));
    return r;
}
__device__ __forceinline__ unsigned long long d2u(double d) {
    return (unsigned long long)__double_as_longlong(d);
}

// ---------------- detect index dtype (int64 vs int32) ----------------
__global__ void detect_idx_kernel(const void* __restrict__ nidx) {
    const int* p = (const int*)nidx;
    int allzero = 1;
    for (int k = 0; k < 1024; k++) {
        if (p[2 * k + 1] != 0) { allzero = 0; break; }
    }
    d_idx64flag = allzero;
}

// ---------------- normalize prototypes ----------------
__global__ void protoN_kernel(const float* __restrict__ proto) {
    int c = threadIdx.x;
    if (c < CC) {
        float s = 0.f;
        for (int k = 0; k < DD; k++) { float v = proto[c * DD + k]; s += v * v; }
        float nrm = fmaxf(sqrtf(s), 1e-12f);
        float inv = 1.f / nrm;
        for (int k = 0; k < DD; k++) d_protoN[c * DD + k] = proto[c * DD + k] * inv;
    }
}

// ---------------- per-point argmax over 7 prototype dots ----------------
__global__ __launch_bounds__(256) void preds_kernel(const float* __restrict__ feat) {
    __shared__ float sp[CC][DD];
    int tid = threadIdx.x;
    for (int i = tid; i < CC * DD; i += 256) sp[i / DD][i % DD] = d_protoN[i];
    __syncthreads();
    int n = blockIdx.x * 256 + tid;
    if (n >= NN) return;
    const float* f = feat + (long long)n * DD;
    float acc[CC];
#pragma unroll
    for (int c = 0; c < CC; c++) acc[c] = 0.f;
    for (int k = 0; k < DD; k++) {
        float fk = f[k];
#pragma unroll
        for (int c = 0; c < CC; c++) acc[c] += fk * sp[c][k];
    }
    float best = acc[0];
    int bi = 0;
#pragma unroll
    for (int c = 1; c < CC; c++) {
        if (acc[c] > best) { best = acc[c]; bi = c; }
    }
    d_preds[n] = bi;
}

// ---------------- KNN consistency + prior filters -> mask ----------------
__global__ __launch_bounds__(256) void mask_kernel(const float* __restrict__ coords,
                                                   const float* __restrict__ normz,
                                                   const void* __restrict__ nidx) {
    int n = blockIdx.x * 256 + threadIdx.x;
    if (n >= NN) return;
    int p = d_preds[n];
    int is64 = d_idx64flag;
    const long long* ni64 = (const long long*)nidx;
    const int*       ni32 = (const int*)nidx;
    int cnt = 0;
#pragma unroll
    for (int k = 0; k < KK; k++) {
        long long raw = is64 ? ni64[(long long)n * KK + k]
                             : (long long)ni32[(long long)n * KK + k];
        unsigned int idx = (unsigned int)raw;
        if (idx >= NN) idx = 0;
        cnt += (d_preds[idx] == p);
    }
    bool cmask = cnt > 16;

    bool plane   = (p == 2) | (p == 3) | (p == 4);
    bool manmade = (p == 5);
    bool other   = (p == 0) | (p == 1) | (p == 6);
    float nz = normz[n];
    float z  = coords[(long long)n * 3 + 2];
    bool ground = plane && (nz > 0.9f) && (z < -10.0f);
    bool g = ground || other || manmade;
    bool m = (manmade && (nz < 0.1f)) || other || plane;
    d_maskf[n] = (cmask && g && m) ? 1.f : 0.f;
}

// ---------------- feat_h = relu(feat @ W) with f32x2 ----------------
__global__ __launch_bounds__(256) void feath_kernel(const float* __restrict__ feat,
                                                    const float* __restrict__ w) {
    __shared__ __align__(16) float As[32][68];   // As[k][m] = feat[n0+m][k0+k]
    __shared__ __align__(16) float Bs[32][68];   // Bs[k][j] = w[k0+k][h0+j]
    int tid = threadIdx.x;
    int h0 = blockIdx.x * 64;
    int n0 = blockIdx.y * 64;
    int tx = tid & 15, ty = tid >> 4;
    unsigned long long acc[4][2];
#pragma unroll
    for (int r = 0; r < 4; r++) { acc[r][0] = 0ull; acc[r][1] = 0ull; }

    for (int k0 = 0; k0 < DD; k0 += 32) {
        for (int i = tid; i < 64 * 32; i += 256) {
            int k = i & 31, m = i >> 5;
            int n = n0 + m;
            As[k][m] = (n < NN) ? feat[(long long)n * DD + k0 + k] : 0.f;
        }
        for (int i = tid; i < 32 * 64; i += 256) {
            int k = i >> 6, m = i & 63;
            Bs[k][m] = w[(k0 + k) * HH + h0 + m];
        }
        __syncthreads();
#pragma unroll
        for (int k = 0; k < 32; k++) {
            float4 a = *reinterpret_cast<const float4*>(&As[k][ty << 2]);
            double2 bd = *reinterpret_cast<const double2*>(&Bs[k][tx << 2]);
            unsigned long long b0 = d2u(bd.x), b1 = d2u(bd.y);
            unsigned long long a0 = dup2(a.x), a1 = dup2(a.y), a2 = dup2(a.z), a3 = dup2(a.w);
            acc[0][0] = ffma2(a0, b0, acc[0][0]); acc[0][1] = ffma2(a0, b1, acc[0][1]);
            acc[1][0] = ffma2(a1, b0, acc[1][0]); acc[1][1] = ffma2(a1, b1, acc[1][1]);
            acc[2][0] = ffma2(a2, b0, acc[2][0]); acc[2][1] = ffma2(a2, b1, acc[2][1]);
            acc[3][0] = ffma2(a3, b0, acc[3][0]); acc[3][1] = ffma2(a3, b1, acc[3][1]);
        }
        __syncthreads();
    }
#pragma unroll
    for (int r = 0; r < 4; r++) {
        int n = n0 + (ty << 2) + r;
        if (n < NN) {
            float2 v0 = up2(acc[r][0]);
            float2 v1 = up2(acc[r][1]);
            float4 o = make_float4(fmaxf(v0.x, 0.f), fmaxf(v0.y, 0.f),
                                   fmaxf(v1.x, 0.f), fmaxf(v1.y, 0.f));
            *reinterpret_cast<float4*>(&d_featH[(long long)n * HH + h0 + (tx << 2)]) = o;
        }
    }
}

// ---------------- Gram split-K: lower-triangle 128x128 tiles, f32x2 ----------------
__global__ __launch_bounds__(256) void gram2_kernel() {
    __shared__ __align__(16) float As[8][132];   // masked rows (i side)
    __shared__ __align__(16) float Bs[8][132];
    int t = blockIdx.x, sp = blockIdx.y;
    int bi = 0;
    while ((bi + 1) * (bi + 2) / 2 <= t) bi++;
    int bj = t - bi * (bi + 1) / 2;
    int h10 = bi * 128, h20 = bj * 128;
    int tid = threadIdx.x;
    int r = tid >> 5, c4 = tid & 31;       // loader mapping: 8 rows x 32 float4
    int tx = tid & 15, ty = tid >> 4;      // compute mapping

    unsigned long long acc[8][4];
#pragma unroll
    for (int a = 0; a < 8; a++)
#pragma unroll
        for (int b = 0; b < 4; b++) acc[a][b] = 0ull;

    int nbase = sp * NSPL;
    const float* fa = &d_featH[(long long)(nbase + r) * HH + h10 + (c4 << 2)];
    const float* fb = &d_featH[(long long)(nbase + r) * HH + h20 + (c4 << 2)];
    const float* fm = &d_maskf[nbase + r];
    float4 pa = *reinterpret_cast<const float4*>(fa);
    float4 pb = *reinterpret_cast<const float4*>(fb);
    float pmv = *fm;

    for (int it = 0; it < GITER; it++) {
        __syncthreads();
        *reinterpret_cast<float4*>(&As[r][c4 << 2]) =
            make_float4(pa.x * pmv, pa.y * pmv, pa.z * pmv, pa.w * pmv);
        *reinterpret_cast<float4*>(&Bs[r][c4 << 2]) = pb;
        if (it + 1 < GITER) {
            fa += 8 * HH; fb += 8 * HH; fm += 8;
            pa = *reinterpret_cast<const float4*>(fa);
            pb = *reinterpret_cast<const float4*>(fb);
            pmv = *fm;
        }
        __syncthreads();
#pragma unroll
        for (int k = 0; k < 8; k++) {
            float4 a0 = *reinterpret_cast<const float4*>(&As[k][ty << 2]);
            float4 a1 = *reinterpret_cast<const float4*>(&As[k][64 + (ty << 2)]);
            double2 bd0 = *reinterpret_cast<const double2*>(&Bs[k][tx << 2]);
            double2 bd1 = *reinterpret_cast<const double2*>(&Bs[k][64 + (tx << 2)]);
            unsigned long long bp0 = d2u(bd0.x), bp1 = d2u(bd0.y);
            unsigned long long bp2 = d2u(bd1.x), bp3 = d2u(bd1.y);
            float av[8] = {a0.x, a0.y, a0.z, a0.w, a1.x, a1.y, a1.z, a1.w};
#pragma unroll
            for (int rr = 0; rr < 8; rr++) {
                unsigned long long ap = dup2(av[rr]);
                acc[rr][0] = ffma2(ap, bp0, acc[rr][0]);
                acc[rr][1] = ffma2(ap, bp1, acc[rr][1]);
                acc[rr][2] = ffma2(ap, bp2, acc[rr][2]);
                acc[rr][3] = ffma2(ap, bp3, acc[rr][3]);
            }
        }
    }

    float* out = &d_Spart[(sp * NTRI + t) * 128 * 128];
#pragma unroll
    for (int rg = 0; rg < 2; rg++) {
#pragma unroll
        for (int rr = 0; rr < 4; rr++) {
            int ridx = rg * 4 + rr;
            int row = rg * 64 + (ty << 2) + rr;
            float2 v0 = up2(acc[ridx][0]);
            float2 v1 = up2(acc[ridx][1]);
            float2 v2 = up2(acc[ridx][2]);
            float2 v3 = up2(acc[ridx][3]);
            *reinterpret_cast<float4*>(&out[row * 128 + (tx << 2)]) =
                make_float4(v0.x, v0.y, v1.x, v1.y);
            *reinterpret_cast<float4*>(&out[row * 128 + 64 + (tx << 2)]) =
                make_float4(v2.x, v2.y, v3.x, v3.y);
        }
    }
}

// ---------------- reduce split-K partials into d_Gn lower triangle ----------------
__global__ __launch_bounds__(256) void greduce_kernel() {
    int t = blockIdx.x;
    int bi = 0;
    while ((bi + 1) * (bi + 2) / 2 <= t) bi++;
    int bj = t - bi * (bi + 1) / 2;
    for (int i = threadIdx.x; i < 128 * 128 / 4; i += 256) {
        float4 s = make_float4(0.f, 0.f, 0.f, 0.f);
#pragma unroll
        for (int sp = 0; sp < GSPLIT; sp++) {
            float4 v = *reinterpret_cast<const float4*>(
                &d_Spart[(sp * NTRI + t) * 128 * 128 + i * 4]);
            s.x += v.x; s.y += v.y; s.z += v.z; s.w += v.w;
        }
        int r = (i * 4) >> 7, c = (i * 4) & 127;
        *reinterpret_cast<float4*>(&d_Gn[(bi * 128 + r) * HH + bj * 128 + c]) = s;
    }
}

// ---------------- mirror + Gin + ridge -> fp64 ----------------
__global__ void convm_kernel(const float* __restrict__ Gin) {
    int idx = blockIdx.x * 256 + threadIdx.x;
    int i = idx >> 10, j = idx & 1023;
    float v = (i >= j) ? d_Gn[i * HH + j] : d_Gn[j * HH + i];
    d_Gd[idx] = (double)(v + Gin[idx]) + ((i == j) ? 100.0 : 0.0);
}

// ---------------- Qn partials ----------------
__global__ __launch_bounds__(256) void qpart_kernel() {
    int h = blockIdx.x * 256 + threadIdx.x;
    int chunk = blockIdx.y;
    int nb = chunk * NPER;
    float a0 = 0, a1 = 0, a2 = 0, a3 = 0, a4 = 0, a5 = 0, a6 = 0;
    for (int t = 0; t < NPER; t++) {
        int n = nb + t;
        float mv = d_maskf[n];
        if (mv != 0.f) {
            float v = d_featH[(long long)n * HH + h];
            int p = d_preds[n];
            a0 += (p == 0) ? v : 0.f;
            a1 += (p == 1) ? v : 0.f;
            a2 += (p == 2) ? v : 0.f;
            a3 += (p == 3) ? v : 0.f;
            a4 += (p == 4) ? v : 0.f;
            a5 += (p == 5) ? v : 0.f;
            a6 += (p == 6) ? v : 0.f;
        }
    }
    int o = (chunk * HH + h) * CC;
    d_Qpart[o + 0] = a0; d_Qpart[o + 1] = a1; d_Qpart[o + 2] = a2; d_Qpart[o + 3] = a3;
    d_Qpart[o + 4] = a4; d_Qpart[o + 5] = a5; d_Qpart[o + 6] = a6;
}

__global__ void qreduce_kernel(const float* __restrict__ Qin) {
    int idx = blockIdx.x * 256 + threadIdx.x;
    if (idx >= HH * CC) return;
    float s = Qin[idx];
    for (int ch = 0; ch < NCHUNK; ch++) s += d_Qpart[ch * HH * CC + idx];
    d_Qn[idx] = s;
}

// ---------------- blocked fp64 Cholesky (lower), block = 64 ----------------
__global__ void chol_potf2(int kb) {
    int i = threadIdx.x;  // 64 threads
    int off = kb * 64;
    __shared__ double s[64][65];
    for (int j = 0; j < 64; j++) s[i][j] = d_Gd[(off + i) * HH + off + j];
    __syncthreads();
    for (int j = 0; j < 64; j++) {
        if (i == j) s[j][j] = sqrt(s[j][j]);
        __syncthreads();
        if (i > j) s[i][j] /= s[j][j];
        __syncthreads();
        if (i > j) {
            double lij = s[i][j];
            for (int k = j + 1; k <= i; k++) s[i][k] -= lij * s[k][j];
        }
        __syncthreads();
    }
    for (int j = 0; j <= i; j++) d_Gd[(off + i) * HH + off + j] = s[i][j];
    d_dinv[off + i] = 1.0 / s[i][i];
}

// trsm: update-form forward substitution (no serial reduction chain)
__global__ __launch_bounds__(128) void chol_trsm(int kb) {
    int off = kb * 64;
    int base = off + 64;
    __shared__ double L[64][65];
    __shared__ double di[64];
    for (int i = threadIdx.x; i < 64 * 64; i += 128)
        L[i >> 6][i & 63] = d_Gd[(off + (i >> 6)) * HH + off + (i & 63)];
    if (threadIdx.x < 64) di[threadIdx.x] = d_dinv[off + threadIdx.x];
    __syncthreads();
    int r = base + blockIdx.x * 128 + threadIdx.x;
    if (r >= HH) return;
    double* a = &d_Gd[r * HH + off];
    double x[64];
#pragma unroll
    for (int j = 0; j < 64; j++) x[j] = a[j];
#pragma unroll
    for (int j = 0; j < 64; j++) {
        double xj = x[j] * di[j];
        x[j] = xj;
#pragma unroll
        for (int tt = j + 1; tt < 64; tt++) x[tt] -= xj * L[tt][j];
    }
#pragma unroll
    for (int j = 0; j < 64; j++) a[j] = x[j];
}

__global__ __launch_bounds__(256) void chol_syrk(int kb) {
    int off = kb * 64;
    int base = off + 64;
    int i0 = base + blockIdx.y * 32;
    int j0 = base + blockIdx.x * 32;
    if (j0 > i0) return;
    __shared__ double Li[32][65];
    __shared__ double Lj[32][65];
    int tid = threadIdx.x;
    for (int i = tid; i < 32 * 64; i += 256) {
        int ii = i >> 6, t = i & 63;
        Li[ii][t] = d_Gd[(i0 + ii) * HH + off + t];
        Lj[ii][t] = d_Gd[(j0 + ii) * HH + off + t];
    }
    __syncthreads();
    int tx = tid & 31, ty = tid >> 5;
    double acc[4] = {0, 0, 0, 0};
    for (int t = 0; t < 64; t++) {
        double bj = Lj[tx][t];
#pragma unroll
        for (int r = 0; r < 4; r++) acc[r] += Li[(ty << 2) + r][t] * bj;
    }
#pragma unroll
    for (int r = 0; r < 4; r++) {
        int i = i0 + (ty << 2) + r;
        int j = j0 + tx;
        if (j <= i) d_Gd[i * HH + j] -= acc[r];
    }
}

// ---------------- triangular solves: L y = Qn ; L^T wo = y (7 RHS) ----------------
__global__ __launch_bounds__(1024) void chol_solve() {
    int i = threadIdx.x;
    __shared__ double shy[64][CC];
    double y[CC];
#pragma unroll
    for (int c = 0; c < CC; c++) y[c] = (double)d_Qn[i * CC + c];
    for (int jb = 0; jb < HH; jb += 64) {
        for (int j = jb; j < jb + 64; j++) {
            if (i == j) {
                double dgl = d_dinv[j];
#pragma unroll
                for (int c = 0; c < CC; c++) { y[c] *= dgl; shy[j - jb][c] = y[c]; }
            }
            __syncthreads();
            if (i > j && i < jb + 64) {
                double lij = d_Gd[i * HH + j];
#pragma unroll
                for (int c = 0; c < CC; c++) y[c] -= lij * shy[j - jb][c];
            }
            __syncthreads();
        }
        if (i >= jb + 64) {
            for (int t = 0; t < 64; t++) {
                double lij = d_Gd[i * HH + jb + t];
#pragma unroll
                for (int c = 0; c < CC; c++) y[c] -= lij * shy[t][c];
            }
        }
        __syncthreads();
    }
    for (int jb = HH - 64; jb >= 0; jb -= 64) {
        for (int j = jb + 63; j >= jb; j--) {
            if (i == j) {
                double dgl = d_dinv[j];
#pragma unroll
                for (int c = 0; c < CC; c++) { y[c] *= dgl; shy[j - jb][c] = y[c]; }
            }
            __syncthreads();
            if (i >= jb && i < j) {
                double lji = d_Gd[j * HH + i];
#pragma unroll
                for (int c = 0; c < CC; c++) y[c] -= lji * shy[j - jb][c];
            }
            __syncthreads();
        }
        if (i < jb) {
            for (int t = 0; t < 64; t++) {
                double lji = d_Gd[(jb + t) * HH + i];
#pragma unroll
                for (int c = 0; c < CC; c++) y[c] -= lji * shy[t][c];
            }
        }
        __syncthreads();
    }
#pragma unroll
    for (int c = 0; c < CC; c++) d_wo[i * CC + c] = (float)y[c];
}

// ---------------- pred_domain = featH @ wo ----------------
__global__ __launch_bounds__(256) void final_kernel(float* __restrict__ out) {
    __shared__ float sw[HH * CC];
    int tid = threadIdx.x;
    for (int i = tid; i < HH * CC; i += 256) sw[i] = d_wo[i];
    __syncthreads();
    int warp = tid >> 5, lane = tid & 31;
    int n = blockIdx.x * 8 + warp;
    if (n >= NN) return;
    const float* a = &d_featH[(long long)n * HH];
    float acc[CC];
#pragma unroll
    for (int c = 0; c < CC; c++) acc[c] = 0.f;
    for (int h = lane; h < HH; h += 32) {
        float v = a[h];
#pragma unroll
        for (int c = 0; c < CC; c++) acc[c] += v * sw[h * CC + c];
    }
#pragma unroll
    for (int c = 0; c < CC; c++) {
#pragma unroll
        for (int off = 16; off > 0; off >>= 1)
            acc[c] += __shfl_xor_sync(0xffffffffu, acc[c], off);
    }
    if (lane == 0) {
#pragma unroll
        for (int c = 0; c < CC; c++) out[(long long)n * CC + c] = acc[c];
    }
}

// ---------------- launcher ----------------
extern "C" void kernel_launch(void* const* d_in, const int* in_sizes, int n_in,
                              void* d_out, int out_size) {
    const float* feat   = (const float*)d_in[0];
    const float* proto  = (const float*)d_in[1];
    const float* wrand  = (const float*)d_in[2];
    const float* Qin    = (const float*)d_in[3];
    const float* Gin    = (const float*)d_in[4];
    const float* coords = (const float*)d_in[5];
    const float* normz  = (const float*)d_in[6];
    const void*  nidx   = (const void*)d_in[7];
    float* out = (float*)d_out;

    detect_idx_kernel<<<1, 1>>>(nidx);
    protoN_kernel<<<1, 32>>>(proto);
    preds_kernel<<<(NN + 255) / 256, 256>>>(feat);
    mask_kernel<<<(NN + 255) / 256, 256>>>(coords, normz, nidx);
    feath_kernel<<<dim3(HH / 64, (NN + 63) / 64), 256>>>(feat, wrand);
    gram2_kernel<<<dim3(NTRI, GSPLIT), 256>>>();
    greduce_kernel<<<NTRI, 256>>>();
    qpart_kernel<<<dim3(HH / 256, NCHUNK), 256>>>();
    qreduce_kernel<<<(HH * CC + 255) / 256, 256>>>(Qin);
    convm_kernel<<<(HH * HH) / 256, 256>>>(Gin);

    for (int kb = 0; kb < HH / 64; kb++) {
        chol_potf2<<<1, 64>>>(kb);
        int rows = HH - (kb * 64 + 64);
        if (rows > 0) {
            chol_trsm<<<(rows + 127) / 128, 128>>>(kb);
            int nt = (rows + 31) / 32;
            chol_syrk<<<dim3(nt, nt), 256>>>(kb);
        }
    }
    chol_solve<<<1, 1024>>>();
    final_kernel<<<(NN + 7) / 8, 256>>>(out);
}

// round 8
// speedup vs baseline: 2.1063x; 1.0050x over previous
#include <cuda_runtime.h>
#include <cuda_bf16.h>
#include <math.h>
#include <stdint.h>

#define NN 100000
#define KK 20
#define DD 96
#define HH 1024
#define CC 7
#define KPAD 100096               // 1564 * 64
#define NCHK (KPAD / 64)          // 1564
#define GSPLIT 4
#define CPT (NCHK / GSPLIT)       // 391 k-chunks per split
#define NTRI 36
#define NCHUNK 32
#define NPER (NN / NCHUNK)        // 3125

// gram smem geometry: 4 tiles of 128 rows x 72 bf16 (64 used + 8 pad), double buffered
#define GS_ROWB 144               // bytes per padded row
#define GS_TILE (128 * GS_ROWB)   // 18432 B
#define GS_STAGE (4 * GS_TILE)    // 73728 B
#define GS_TOTAL (2 * GS_STAGE)   // 147456 B

// ---------------- scratch (static device globals; no allocations) ----------------
static __device__ int           d_preds[NN];
static __device__ float         d_maskf[NN];
static __device__ float         d_featH[(long long)NN * HH];        // 400 MB fp32
static __device__ __nv_bfloat16 d_FhThi[(long long)HH * KPAD];      // transposed hi
static __device__ __nv_bfloat16 d_FhTlo[(long long)HH * KPAD];      // transposed lo
static __device__ __nv_bfloat16 d_FhThiM[(long long)HH * KPAD];     // masked hi
static __device__ __nv_bfloat16 d_FhTloM[(long long)HH * KPAD];     // masked lo
static __device__ float         d_Spart[GSPLIT * NTRI * 128 * 128]; // split-K partials
static __device__ float         d_Qpart[NCHUNK * HH * CC];
static __device__ float         d_Qn[HH * CC];
static __device__ float         d_Gn[HH * HH];
static __device__ double        d_Gd[HH * HH];
static __device__ double        d_dinv[HH];
static __device__ float         d_wo[HH * CC];

// ---------------- ptx helpers (base-target features only: sm_80+) ----------------
__device__ __forceinline__ uint32_t smem_to_u32(const void* smem_ptr) {
    uint32_t addr;
    asm("{ .reg .u64 tmp; cvta.to.shared.u64 tmp, %1; cvt.u32.u64 %0, tmp; }"
        : "=r"(addr) : "l"(smem_ptr));
    return addr;
}
#define CP_ASYNC16(dst, src) \
    asm volatile("cp.async.cg.shared.global [%0], [%1], 16;" :: "r"(dst), "l"(src))
#define CP_COMMIT() asm volatile("cp.async.commit_group;" ::: "memory")
#define CP_WAIT1()  asm volatile("cp.async.wait_group 1;" ::: "memory")
#define CP_WAIT0()  asm volatile("cp.async.wait_group 0;" ::: "memory")
#define LDSM4(r, addr) \
    asm volatile("ldmatrix.sync.aligned.m8n8.x4.shared.b16 {%0,%1,%2,%3}, [%4];" \
        : "=r"((r)[0]), "=r"((r)[1]), "=r"((r)[2]), "=r"((r)[3]) : "r"(addr))
#define MMA16816(c, a, b) \
    asm volatile("mma.sync.aligned.m16n8k16.row.col.f32.bf16.bf16.f32 " \
        "{%0,%1,%2,%3}, {%4,%5,%6,%7}, {%8,%9}, {%0,%1,%2,%3};" \
        : "+f"((c)[0]), "+f"((c)[1]), "+f"((c)[2]), "+f"((c)[3]) \
        : "r"((a)[0]), "r"((a)[1]), "r"((a)[2]), "r"((a)[3]), "r"((b)[0]), "r"((b)[1]))

// ---------------- f32x2 helpers (feath) ----------------
__device__ __forceinline__ unsigned long long ffma2(unsigned long long a,
                                                    unsigned long long b,
                                                    unsigned long long c) {
    unsigned long long d;
    asm("fma.rn.f32x2 %0, %1, %2, %3;" : "=l"(d) : "l"(a), "l"(b), "l"(c));
    return d;
}
__device__ __forceinline__ unsigned long long dup2(float x) {
    unsigned long long d;
    asm("mov.b64 %0, {%1, %1};" : "=l"(d) : "f"(x));
    return d;
}
__device__ __forceinline__ float2 up2(unsigned long long v) {
    float2 r;
    asm("mov.b64 {%0, %1}, %2;" : "=f"(r.x), "=f"(r.y) : "l"(v));
    return r;
}
__device__ __forceinline__ unsigned long long d2u(double d) {
    return (unsigned long long)__double_as_longlong(d);
}

// ---------------- launch 0: preds (with inline proto normalize) ----------------
__global__ __launch_bounds__(256) void preds_kernel(const float* __restrict__ feat,
                                                    const float* __restrict__ proto) {
    __shared__ float sp[CC][DD];
    int tid = threadIdx.x;
    if (tid < CC) {
        float s = 0.f;
        for (int k = 0; k < DD; k++) { float v = proto[tid * DD + k]; s += v * v; }
        float inv = 1.f / fmaxf(sqrtf(s), 1e-12f);
        for (int k = 0; k < DD; k++) sp[tid][k] = proto[tid * DD + k] * inv;
    }
    __syncthreads();
    int n = blockIdx.x * 256 + tid;
    if (n >= NN) return;
    const float* f = feat + (long long)n * DD;
    float acc[CC];
#pragma unroll
    for (int c = 0; c < CC; c++) acc[c] = 0.f;
    for (int k = 0; k < DD; k++) {
        float fk = f[k];
#pragma unroll
        for (int c = 0; c < CC; c++) acc[c] += fk * sp[c][k];
    }
    float best = acc[0];
    int bi = 0;
#pragma unroll
    for (int c = 1; c < CC; c++)
        if (acc[c] > best) { best = acc[c]; bi = c; }
    d_preds[n] = bi;
}

// ---------------- launch 1: mask (inline idx-dtype detect) ----------------
__global__ __launch_bounds__(256) void mask_kernel(const float* __restrict__ coords,
                                                   const float* __restrict__ normz,
                                                   const void* __restrict__ nidx) {
    int n = blockIdx.x * 256 + threadIdx.x;
    if (n >= NN) return;
    const int* pw = (const int*)nidx;
    int is64 = 1;
#pragma unroll
    for (int k = 1; k < 40; k += 2) is64 &= (pw[k] == 0);

    int p = d_preds[n];
    const long long* ni64 = (const long long*)nidx;
    const int*       ni32 = (const int*)nidx;
    int cnt = 0;
#pragma unroll
    for (int k = 0; k < KK; k++) {
        long long raw = is64 ? ni64[(long long)n * KK + k]
                             : (long long)ni32[(long long)n * KK + k];
        unsigned int idx = (unsigned int)raw;
        if (idx >= NN) idx = 0;
        cnt += (d_preds[idx] == p);
    }
    bool cmask = cnt > 16;
    bool plane   = (p == 2) | (p == 3) | (p == 4);
    bool manmade = (p == 5);
    bool other   = (p == 0) | (p == 1) | (p == 6);
    float nz = normz[n];
    float z  = coords[(long long)n * 3 + 2];
    bool ground = plane && (nz > 0.9f) && (z < -10.0f);
    bool g = ground || other || manmade;
    bool m = (manmade && (nz < 0.1f)) || other || plane;
    d_maskf[n] = (cmask && g && m) ? 1.f : 0.f;
}

// ---------------- launch 2: feat_h = relu(feat @ W); fp32 + bf16 hi/lo (+masked) ----------------
__global__ __launch_bounds__(256) void feath_kernel(const float* __restrict__ feat,
                                                    const float* __restrict__ w) {
    __shared__ __align__(16) float As[32][68];
    __shared__ __align__(16) float Bs[32][68];
    __shared__ float sT[64][65];
    int tid = threadIdx.x;
    int h0 = blockIdx.x * 64;
    int n0 = blockIdx.y * 64;     // up to KPAD-64
    int tx = tid & 15, ty = tid >> 4;
    unsigned long long acc[4][2];
#pragma unroll
    for (int r = 0; r < 4; r++) { acc[r][0] = 0ull; acc[r][1] = 0ull; }

    for (int k0 = 0; k0 < DD; k0 += 32) {
        for (int i = tid; i < 64 * 32; i += 256) {
            int k = i & 31, m = i >> 5;
            int n = n0 + m;
            As[k][m] = (n < NN) ? feat[(long long)n * DD + k0 + k] : 0.f;
        }
        for (int i = tid; i < 32 * 64; i += 256) {
            int k = i >> 6, m = i & 63;
            Bs[k][m] = w[(k0 + k) * HH + h0 + m];
        }
        __syncthreads();
#pragma unroll
        for (int k = 0; k < 32; k++) {
            float4 a = *reinterpret_cast<const float4*>(&As[k][ty << 2]);
            double2 bd = *reinterpret_cast<const double2*>(&Bs[k][tx << 2]);
            unsigned long long b0 = d2u(bd.x), b1 = d2u(bd.y);
            unsigned long long a0 = dup2(a.x), a1 = dup2(a.y), a2 = dup2(a.z), a3 = dup2(a.w);
            acc[0][0] = ffma2(a0, b0, acc[0][0]); acc[0][1] = ffma2(a0, b1, acc[0][1]);
            acc[1][0] = ffma2(a1, b0, acc[1][0]); acc[1][1] = ffma2(a1, b1, acc[1][1]);
            acc[2][0] = ffma2(a2, b0, acc[2][0]); acc[2][1] = ffma2(a2, b1, acc[2][1]);
            acc[3][0] = ffma2(a3, b0, acc[3][0]); acc[3][1] = ffma2(a3, b1, acc[3][1]);
        }
        __syncthreads();
    }
    // relu, fp32 write, stage transpose
#pragma unroll
    for (int r = 0; r < 4; r++) {
        int n = n0 + (ty << 2) + r;
        float2 v0 = up2(acc[r][0]);
        float2 v1 = up2(acc[r][1]);
        float4 o = make_float4(fmaxf(v0.x, 0.f), fmaxf(v0.y, 0.f),
                               fmaxf(v1.x, 0.f), fmaxf(v1.y, 0.f));
        if (n < NN)
            *reinterpret_cast<float4*>(&d_featH[(long long)n * HH + h0 + (tx << 2)]) = o;
        sT[(tx << 2) + 0][(ty << 2) + r] = o.x;
        sT[(tx << 2) + 1][(ty << 2) + r] = o.y;
        sT[(tx << 2) + 2][(ty << 2) + r] = o.z;
        sT[(tx << 2) + 3][(ty << 2) + r] = o.w;
    }
    __syncthreads();
    // transposed bf16 hi/lo + masked variants: row = h, contiguous n
    int hrow = tid >> 2, q = tid & 3;
    size_t gb = (size_t)(h0 + hrow) * KPAD + n0 + q * 16;
    __align__(16) __nv_bfloat16 hb[16], lb[16], mhb[16], mlb[16];
    __nv_bfloat16 zero = __float2bfloat16(0.f);
#pragma unroll
    for (int i = 0; i < 16; i++) {
        int n = n0 + q * 16 + i;
        float v = sT[hrow][q * 16 + i];
        __nv_bfloat16 h = __float2bfloat16(v);
        hb[i] = h;
        lb[i] = __float2bfloat16(v - __bfloat162float(h));
        bool mk = (n < NN) && (d_maskf[n] != 0.f);
        mhb[i] = mk ? hb[i] : zero;
        mlb[i] = mk ? lb[i] : zero;
    }
    *reinterpret_cast<uint4*>(&d_FhThi[gb])      = *reinterpret_cast<uint4*>(&hb[0]);
    *reinterpret_cast<uint4*>(&d_FhThi[gb + 8])  = *reinterpret_cast<uint4*>(&hb[8]);
    *reinterpret_cast<uint4*>(&d_FhTlo[gb])      = *reinterpret_cast<uint4*>(&lb[0]);
    *reinterpret_cast<uint4*>(&d_FhTlo[gb + 8])  = *reinterpret_cast<uint4*>(&lb[8]);
    *reinterpret_cast<uint4*>(&d_FhThiM[gb])     = *reinterpret_cast<uint4*>(&mhb[0]);
    *reinterpret_cast<uint4*>(&d_FhThiM[gb + 8]) = *reinterpret_cast<uint4*>(&mhb[8]);
    *reinterpret_cast<uint4*>(&d_FhTloM[gb])     = *reinterpret_cast<uint4*>(&mlb[0]);
    *reinterpret_cast<uint4*>(&d_FhTloM[gb + 8]) = *reinterpret_cast<uint4*>(&mlb[8]);
}

// ---------------- launch 3: Gram via mma.sync bf16 hi/lo, split-K, cp.async 2-stage ----------------
__global__ __launch_bounds__(256, 1) void gram_hmma_kernel() {
    extern __shared__ __align__(16) char smg[];
    uint32_t sb = smem_to_u32(smg);
    int tid = threadIdx.x;
    int t = blockIdx.x, sp = blockIdx.y;
    int bi = 0;
    while ((bi + 1) * (bi + 2) / 2 <= t) bi++;
    int bj = t - bi * (bi + 1) / 2;
    int h10 = bi * 128, h20 = bj * 128;

    // loader mapping: thread -> (row, 32-col half); 4x cp.async 16B per tile
    int lrow = tid >> 1, lhalf = tid & 1;
    size_t kstart = (size_t)sp * CPT * 64 + lhalf * 32;
    const __nv_bfloat16* sAh = d_FhThiM + (size_t)(h10 + lrow) * KPAD + kstart;
    const __nv_bfloat16* sAl = d_FhTloM + (size_t)(h10 + lrow) * KPAD + kstart;
    const __nv_bfloat16* sBh = d_FhThi  + (size_t)(h20 + lrow) * KPAD + kstart;
    const __nv_bfloat16* sBl = d_FhTlo  + (size_t)(h20 + lrow) * KPAD + kstart;
    uint32_t ldst = sb + lrow * GS_ROWB + lhalf * 64;

    // compute mapping: 8 warps = 2 (M) x 4 (N); warp tile 64x32
    int wid = tid >> 5, lane = tid & 31;
    int mbase = (wid >> 2) * 64, nbase = (wid & 3) * 32;
    int arow = (lane & 7) + ((lane >> 3) & 1) * 8;
    int acol = ((lane >> 4) & 1) * 8;
    int brow = (lane & 7) + ((lane >> 4) & 1) * 8;
    int bcol = ((lane >> 3) & 1) * 8;
    uint32_t aoff[4], boff[2];
#pragma unroll
    for (int mi = 0; mi < 4; mi++)
        aoff[mi] = (uint32_t)(((mbase + mi * 16 + arow) * 72 + acol) * 2);
#pragma unroll
    for (int nj = 0; nj < 2; nj++)
        boff[nj] = (uint32_t)(((nbase + nj * 16 + brow) * 72 + bcol) * 2);

    float acc[4][4][4];
#pragma unroll
    for (int a = 0; a < 4; a++)
#pragma unroll
        for (int b = 0; b < 4; b++)
#pragma unroll
            for (int c = 0; c < 4; c++) acc[a][b][c] = 0.f;

    // prologue: stage 0
    {
        uint32_t base = ldst;
#pragma unroll
        for (int j = 0; j < 4; j++) {
            CP_ASYNC16(base + 0 * GS_TILE + j * 16, sAh + j * 8);
            CP_ASYNC16(base + 1 * GS_TILE + j * 16, sAl + j * 8);
            CP_ASYNC16(base + 2 * GS_TILE + j * 16, sBh + j * 8);
            CP_ASYNC16(base + 3 * GS_TILE + j * 16, sBl + j * 8);
        }
        CP_COMMIT();
    }

    for (int c = 0; c < CPT; c++) {
        if (c + 1 < CPT) {
            uint32_t base = ldst + ((c + 1) & 1) * GS_STAGE;
            size_t ko = (size_t)(c + 1) * 64;
#pragma unroll
            for (int j = 0; j < 4; j++) {
                CP_ASYNC16(base + 0 * GS_TILE + j * 16, sAh + ko + j * 8);
                CP_ASYNC16(base + 1 * GS_TILE + j * 16, sAl + ko + j * 8);
                CP_ASYNC16(base + 2 * GS_TILE + j * 16, sBh + ko + j * 8);
                CP_ASYNC16(base + 3 * GS_TILE + j * 16, sBl + ko + j * 8);
            }
            CP_COMMIT();
            CP_WAIT1();
        } else {
            CP_WAIT0();
        }
        __syncthreads();
        uint32_t stg = sb + (c & 1) * GS_STAGE;
#pragma unroll
        for (int ks = 0; ks < 4; ks++) {
            uint32_t kb = ks * 32;
            uint32_t ah[4][4], al[4][4], bh[4][2], bl[4][2];
#pragma unroll
            for (int mi = 0; mi < 4; mi++)
                LDSM4(ah[mi], stg + 0 * GS_TILE + aoff[mi] + kb);
#pragma unroll
            for (int nj = 0; nj < 2; nj++) {
                uint32_t r[4];
                LDSM4(r, stg + 2 * GS_TILE + boff[nj] + kb);
                bh[nj * 2][0] = r[0]; bh[nj * 2][1] = r[1];
                bh[nj * 2 + 1][0] = r[2]; bh[nj * 2 + 1][1] = r[3];
            }
#pragma unroll
            for (int mi = 0; mi < 4; mi++)
#pragma unroll
                for (int nj = 0; nj < 4; nj++) MMA16816(acc[mi][nj], ah[mi], bh[nj]);
#pragma unroll
            for (int nj = 0; nj < 2; nj++) {
                uint32_t r[4];
                LDSM4(r, stg + 3 * GS_TILE + boff[nj] + kb);
                bl[nj * 2][0] = r[0]; bl[nj * 2][1] = r[1];
                bl[nj * 2 + 1][0] = r[2]; bl[nj * 2 + 1][1] = r[3];
            }
#pragma unroll
            for (int mi = 0; mi < 4; mi++)
#pragma unroll
                for (int nj = 0; nj < 4; nj++) MMA16816(acc[mi][nj], ah[mi], bl[nj]);
#pragma unroll
            for (int mi = 0; mi < 4; mi++)
                LDSM4(al[mi], stg + 1 * GS_TILE + aoff[mi] + kb);
#pragma unroll
            for (int mi = 0; mi < 4; mi++)
#pragma unroll
                for (int nj = 0; nj < 4; nj++) MMA16816(acc[mi][nj], al[mi], bh[nj]);
        }
        __syncthreads();
    }

    // write 128x128 partial tile
    float* out = &d_Spart[(size_t)(sp * NTRI + t) * 128 * 128];
    int g = lane >> 2, q = lane & 3;
#pragma unroll
    for (int mi = 0; mi < 4; mi++) {
#pragma unroll
        for (int nj = 0; nj < 4; nj++) {
            int r0 = mbase + mi * 16 + g;
            int cc = nbase + nj * 8 + q * 2;
            *reinterpret_cast<float2*>(&out[r0 * 128 + cc]) =
                make_float2(acc[mi][nj][0], acc[mi][nj][1]);
            *reinterpret_cast<float2*>(&out[(r0 + 8) * 128 + cc]) =
                make_float2(acc[mi][nj][2], acc[mi][nj][3]);
        }
    }
}

// ---------------- reduce split-K partials into d_Gn lower triangle ----------------
__global__ __launch_bounds__(256) void greduce_kernel() {
    int t = blockIdx.x;
    int bi = 0;
    while ((bi + 1) * (bi + 2) / 2 <= t) bi++;
    int bj = t - bi * (bi + 1) / 2;
    for (int i = threadIdx.x; i < 128 * 128 / 4; i += 256) {
        float4 s = make_float4(0.f, 0.f, 0.f, 0.f);
#pragma unroll
        for (int sp = 0; sp < GSPLIT; sp++) {
            float4 v = *reinterpret_cast<const float4*>(
                &d_Spart[(size_t)(sp * NTRI + t) * 128 * 128 + i * 4]);
            s.x += v.x; s.y += v.y; s.z += v.z; s.w += v.w;
        }
        int r = (i * 4) >> 7, c = (i * 4) & 127;
        *reinterpret_cast<float4*>(&d_Gn[(bi * 128 + r) * HH + bj * 128 + c]) = s;
    }
}

// ---------------- Qn partials ----------------
__global__ __launch_bounds__(256) void qpart_kernel() {
    int h = blockIdx.x * 256 + threadIdx.x;
    int chunk = blockIdx.y;
    int nb = chunk * NPER;
    float a0 = 0, a1 = 0, a2 = 0, a3 = 0, a4 = 0, a5 = 0, a6 = 0;
    for (int t = 0; t < NPER; t++) {
        int n = nb + t;
        float mv = d_maskf[n];
        if (mv != 0.f) {
            float v = d_featH[(long long)n * HH + h];
            int p = d_preds[n];
            a0 += (p == 0) ? v : 0.f;
            a1 += (p == 1) ? v : 0.f;
            a2 += (p == 2) ? v : 0.f;
            a3 += (p == 3) ? v : 0.f;
            a4 += (p == 4) ? v : 0.f;
            a5 += (p == 5) ? v : 0.f;
            a6 += (p == 6) ? v : 0.f;
        }
    }
    int o = (chunk * HH + h) * CC;
    d_Qpart[o + 0] = a0; d_Qpart[o + 1] = a1; d_Qpart[o + 2] = a2; d_Qpart[o + 3] = a3;
    d_Qpart[o + 4] = a4; d_Qpart[o + 5] = a5; d_Qpart[o + 6] = a6;
}

__global__ void qreduce_kernel(const float* __restrict__ Qin) {
    int idx = blockIdx.x * 256 + threadIdx.x;
    if (idx >= HH * CC) return;
    float s = Qin[idx];
    for (int ch = 0; ch < NCHUNK; ch++) s += d_Qpart[ch * HH * CC + idx];
    d_Qn[idx] = s;
}

// ---------------- mirror + Gin + ridge -> fp64 ----------------
__global__ void convm_kernel(const float* __restrict__ Gin) {
    int idx = blockIdx.x * 256 + threadIdx.x;
    int i = idx >> 10, j = idx & 1023;
    float v = (i >= j) ? d_Gn[i * HH + j] : d_Gn[j * HH + i];
    d_Gd[idx] = (double)(v + Gin[idx]) + ((i == j) ? 100.0 : 0.0);
}

// ---------------- blocked fp64 Cholesky (lower), block = 64 ----------------
__global__ void chol_potf2(int kb) {
    int i = threadIdx.x;
    int off = kb * 64;
    __shared__ double s[64][65];
    for (int j = 0; j < 64; j++) s[i][j] = d_Gd[(off + i) * HH + off + j];
    __syncthreads();
    for (int j = 0; j < 64; j++) {
        if (i == j) s[j][j] = sqrt(s[j][j]);
        __syncthreads();
        if (i > j) s[i][j] /= s[j][j];
        __syncthreads();
        if (i > j) {
            double lij = s[i][j];
            for (int k = j + 1; k <= i; k++) s[i][k] -= lij * s[k][j];
        }
        __syncthreads();
    }
    for (int j = 0; j <= i; j++) d_Gd[(off + i) * HH + off + j] = s[i][j];
    d_dinv[off + i] = 1.0 / s[i][i];
}

__global__ __launch_bounds__(128) void chol_trsm(int kb) {
    int off = kb * 64;
    int base = off + 64;
    __shared__ double L[64][65];
    __shared__ double di[64];
    for (int i = threadIdx.x; i < 64 * 64; i += 128)
        L[i >> 6][i & 63] = d_Gd[(off + (i >> 6)) * HH + off + (i & 63)];
    if (threadIdx.x < 64) di[threadIdx.x] = d_dinv[off + threadIdx.x];
    __syncthreads();
    int r = base + blockIdx.x * 128 + threadIdx.x;
    if (r >= HH) return;
    double* a = &d_Gd[r * HH + off];
    double x[64];
#pragma unroll
    for (int j = 0; j < 64; j++) x[j] = a[j];
#pragma unroll
    for (int j = 0; j < 64; j++) {
        double xj = x[j] * di[j];
        x[j] = xj;
#pragma unroll
        for (int tt = j + 1; tt < 64; tt++) x[tt] -= xj * L[tt][j];
    }
#pragma unroll
    for (int j = 0; j < 64; j++) a[j] = x[j];
}

__global__ __launch_bounds__(256) void chol_syrk(int kb) {
    int off = kb * 64;
    int base = off + 64;
    int i0 = base + blockIdx.y * 32;
    int j0 = base + blockIdx.x * 32;
    if (j0 > i0) return;
    __shared__ double Li[32][65];
    __shared__ double Lj[32][65];
    int tid = threadIdx.x;
    for (int i = tid; i < 32 * 64; i += 256) {
        int ii = i >> 6, t = i & 63;
        Li[ii][t] = d_Gd[(i0 + ii) * HH + off + t];
        Lj[ii][t] = d_Gd[(j0 + ii) * HH + off + t];
    }
    __syncthreads();
    int tx = tid & 31, ty = tid >> 5;
    double acc[4] = {0, 0, 0, 0};
    for (int t = 0; t < 64; t++) {
        double bj = Lj[tx][t];
#pragma unroll
        for (int r = 0; r < 4; r++) acc[r] += Li[(ty << 2) + r][t] * bj;
    }
#pragma unroll
    for (int r = 0; r < 4; r++) {
        int i = i0 + (ty << 2) + r;
        int j = j0 + tx;
        if (j <= i) d_Gd[i * HH + j] -= acc[r];
    }
}

// ---------------- triangular solves: L y = Qn ; L^T wo = y (7 RHS) ----------------
__global__ __launch_bounds__(1024) void chol_solve() {
    int i = threadIdx.x;
    __shared__ double shy[64][CC];
    double y[CC];
#pragma unroll
    for (int c = 0; c < CC; c++) y[c] = (double)d_Qn[i * CC + c];
    for (int jb = 0; jb < HH; jb += 64) {
        for (int j = jb; j < jb + 64; j++) {
            if (i == j) {
                double dgl = d_dinv[j];
#pragma unroll
                for (int c = 0; c < CC; c++) { y[c] *= dgl; shy[j - jb][c] = y[c]; }
            }
            __syncthreads();
            if (i > j && i < jb + 64) {
                double lij = d_Gd[i * HH + j];
#pragma unroll
                for (int c = 0; c < CC; c++) y[c] -= lij * shy[j - jb][c];
            }
            __syncthreads();
        }
        if (i >= jb + 64) {
            for (int t = 0; t < 64; t++) {
                double lij = d_Gd[i * HH + jb + t];
#pragma unroll
                for (int c = 0; c < CC; c++) y[c] -= lij * shy[t][c];
            }
        }
        __syncthreads();
    }
    for (int jb = HH - 64; jb >= 0; jb -= 64) {
        for (int j = jb + 63; j >= jb; j--) {
            if (i == j) {
                double dgl = d_dinv[j];
#pragma unroll
                for (int c = 0; c < CC; c++) { y[c] *= dgl; shy[j - jb][c] = y[c]; }
            }
            __syncthreads();
            if (i >= jb && i < j) {
                double lji = d_Gd[j * HH + i];
#pragma unroll
                for (int c = 0; c < CC; c++) y[c] -= lji * shy[j - jb][c];
            }
            __syncthreads();
        }
        if (i < jb) {
            for (int t = 0; t < 64; t++) {
                double lji = d_Gd[(jb + t) * HH + i];
#pragma unroll
                for (int c = 0; c < CC; c++) y[c] -= lji * shy[t][c];
            }
        }
        __syncthreads();
    }
#pragma unroll
    for (int c = 0; c < CC; c++) d_wo[i * CC + c] = (float)y[c];
}

// ---------------- pred_domain = featH @ wo ----------------
__global__ __launch_bounds__(256) void final_kernel(float* __restrict__ out) {
    __shared__ float sw[HH * CC];
    int tid = threadIdx.x;
    for (int i = tid; i < HH * CC; i += 256) sw[i] = d_wo[i];
    __syncthreads();
    int warp = tid >> 5, lane = tid & 31;
    int n = blockIdx.x * 8 + warp;
    if (n >= NN) return;
    const float* a = &d_featH[(long long)n * HH];
    float acc[CC];
#pragma unroll
    for (int c = 0; c < CC; c++) acc[c] = 0.f;
    for (int h = lane; h < HH; h += 32) {
        float v = a[h];
#pragma unroll
        for (int c = 0; c < CC; c++) acc[c] += v * sw[h * CC + c];
    }
#pragma unroll
    for (int c = 0; c < CC; c++) {
#pragma unroll
        for (int off = 16; off > 0; off >>= 1)
            acc[c] += __shfl_xor_sync(0xffffffffu, acc[c], off);
    }
    if (lane == 0) {
#pragma unroll
        for (int c = 0; c < CC; c++) out[(long long)n * CC + c] = acc[c];
    }
}

// ---------------- launcher ----------------
extern "C" void kernel_launch(void* const* d_in, const int* in_sizes, int n_in,
                              void* d_out, int out_size) {
    const float* feat   = (const float*)d_in[0];
    const float* proto  = (const float*)d_in[1];
    const float* wrand  = (const float*)d_in[2];
    const float* Qin    = (const float*)d_in[3];
    const float* Gin    = (const float*)d_in[4];
    const float* coords = (const float*)d_in[5];
    const float* normz  = (const float*)d_in[6];
    const void*  nidx   = (const void*)d_in[7];
    float* out = (float*)d_out;

    cudaFuncSetAttribute(gram_hmma_kernel,
                         cudaFuncAttributeMaxDynamicSharedMemorySize, GS_TOTAL);

    preds_kernel<<<(NN + 255) / 256, 256>>>(feat, proto);                 // 0
    mask_kernel<<<(NN + 255) / 256, 256>>>(coords, normz, nidx);          // 1
    feath_kernel<<<dim3(HH / 64, KPAD / 64), 256>>>(feat, wrand);         // 2
    gram_hmma_kernel<<<dim3(NTRI, GSPLIT), 256, GS_TOTAL>>>();            // 3 <- ncu slot
    greduce_kernel<<<NTRI, 256>>>();                                      // 4
    qpart_kernel<<<dim3(HH / 256, NCHUNK), 256>>>();
    qreduce_kernel<<<(HH * CC + 255) / 256, 256>>>(Qin);
    convm_kernel<<<(HH * HH) / 256, 256>>>(Gin);

    for (int kb = 0; kb < HH / 64; kb++) {
        chol_potf2<<<1, 64>>>(kb);
        int rows = HH - (kb * 64 + 64);
        if (rows > 0) {
            chol_trsm<<<(rows + 127) / 128, 128>>>(kb);
            int nt = (rows + 31) / 32;
            chol_syrk<<<dim3(nt, nt), 256>>>(kb);
        }
    }
    chol_solve<<<1, 1024>>>();
    final_kernel<<<(NN + 7) / 8, 256>>>(out);
}

// round 9
// speedup vs baseline: 4.7836x; 2.2711x over previous
#include <cuda_runtime.h>
#include <cuda_bf16.h>
#include <math.h>
#include <stdint.h>

#define NN 100000
#define KK 20
#define DD 96
#define HH 1024
#define CC 7
#define KPAD 100096               // 1564 * 64
#define NCHK (KPAD / 64)          // 1564
#define GSPLIT 4
#define CPT (NCHK / GSPLIT)       // 391 k-chunks per split
#define NTRI 36
#define NCHUNK 32
#define NPER (NN / NCHUNK)        // 3125

// gram smem geometry: 4 tiles of 128 rows x 72 bf16 (64 used + 8 pad), double buffered
#define GS_ROWB 144               // bytes per padded row
#define GS_TILE (128 * GS_ROWB)   // 18432 B
#define GS_STAGE (4 * GS_TILE)    // 73728 B
#define GS_TOTAL (2 * GS_STAGE)   // 147456 B

// ---------------- scratch (static device globals; no allocations) ----------------
static __device__ int           d_preds[NN];
static __device__ float         d_maskf[NN];
static __device__ float         d_featH[(long long)NN * HH];        // 400 MB fp32
static __device__ __nv_bfloat16 d_FhThi[(long long)HH * KPAD];      // transposed hi
static __device__ __nv_bfloat16 d_FhTlo[(long long)HH * KPAD];      // transposed lo
static __device__ __nv_bfloat16 d_FhThiM[(long long)HH * KPAD];     // masked hi
static __device__ __nv_bfloat16 d_FhTloM[(long long)HH * KPAD];     // masked lo
static __device__ float         d_Spart[GSPLIT * NTRI * 128 * 128]; // split-K partials
static __device__ float         d_Qpart[NCHUNK * HH * CC];
static __device__ float         d_Qn[HH * CC];
static __device__ float         d_Gn[HH * HH];
static __device__ float         d_GA[HH * HH];   // A = G + Gin + ridge (kept for IR)
static __device__ float         d_Gf[HH * HH];   // factored in place (fp32 Cholesky)
static __device__ float         d_dinvf[HH];
static __device__ float         d_res[HH * CC];
static __device__ float         d_wo[HH * CC];

// ---------------- ptx helpers (base-target features only: sm_80+) ----------------
__device__ __forceinline__ uint32_t smem_to_u32(const void* smem_ptr) {
    uint32_t addr;
    asm("{ .reg .u64 tmp; cvta.to.shared.u64 tmp, %1; cvt.u32.u64 %0, tmp; }"
        : "=r"(addr) : "l"(smem_ptr));
    return addr;
}
#define CP_ASYNC16(dst, src) \
    asm volatile("cp.async.cg.shared.global [%0], [%1], 16;" :: "r"(dst), "l"(src))
#define CP_COMMIT() asm volatile("cp.async.commit_group;" ::: "memory")
#define CP_WAIT1()  asm volatile("cp.async.wait_group 1;" ::: "memory")
#define CP_WAIT0()  asm volatile("cp.async.wait_group 0;" ::: "memory")
#define LDSM4(r, addr) \
    asm volatile("ldmatrix.sync.aligned.m8n8.x4.shared.b16 {%0,%1,%2,%3}, [%4];" \
        : "=r"((r)[0]), "=r"((r)[1]), "=r"((r)[2]), "=r"((r)[3]) : "r"(addr))
#define MMA16816(c, a, b) \
    asm volatile("mma.sync.aligned.m16n8k16.row.col.f32.bf16.bf16.f32 " \
        "{%0,%1,%2,%3}, {%4,%5,%6,%7}, {%8,%9}, {%0,%1,%2,%3};" \
        : "+f"((c)[0]), "+f"((c)[1]), "+f"((c)[2]), "+f"((c)[3]) \
        : "r"((a)[0]), "r"((a)[1]), "r"((a)[2]), "r"((a)[3]), "r"((b)[0]), "r"((b)[1]))

// ---------------- f32x2 helpers (feath) ----------------
__device__ __forceinline__ unsigned long long ffma2(unsigned long long a,
                                                    unsigned long long b,
                                                    unsigned long long c) {
    unsigned long long d;
    asm("fma.rn.f32x2 %0, %1, %2, %3;" : "=l"(d) : "l"(a), "l"(b), "l"(c));
    return d;
}
__device__ __forceinline__ unsigned long long dup2(float x) {
    unsigned long long d;
    asm("mov.b64 %0, {%1, %1};" : "=l"(d) : "f"(x));
    return d;
}
__device__ __forceinline__ float2 up2(unsigned long long v) {
    float2 r;
    asm("mov.b64 {%0, %1}, %2;" : "=f"(r.x), "=f"(r.y) : "l"(v));
    return r;
}
__device__ __forceinline__ unsigned long long d2u(double d) {
    return (unsigned long long)__double_as_longlong(d);
}

// ---------------- launch 0: preds (with inline proto normalize) ----------------
__global__ __launch_bounds__(256) void preds_kernel(const float* __restrict__ feat,
                                                    const float* __restrict__ proto) {
    __shared__ float sp[CC][DD];
    int tid = threadIdx.x;
    if (tid < CC) {
        float s = 0.f;
        for (int k = 0; k < DD; k++) { float v = proto[tid * DD + k]; s += v * v; }
        float inv = 1.f / fmaxf(sqrtf(s), 1e-12f);
        for (int k = 0; k < DD; k++) sp[tid][k] = proto[tid * DD + k] * inv;
    }
    __syncthreads();
    int n = blockIdx.x * 256 + tid;
    if (n >= NN) return;
    const float* f = feat + (long long)n * DD;
    float acc[CC];
#pragma unroll
    for (int c = 0; c < CC; c++) acc[c] = 0.f;
    for (int k = 0; k < DD; k++) {
        float fk = f[k];
#pragma unroll
        for (int c = 0; c < CC; c++) acc[c] += fk * sp[c][k];
    }
    float best = acc[0];
    int bi = 0;
#pragma unroll
    for (int c = 1; c < CC; c++)
        if (acc[c] > best) { best = acc[c]; bi = c; }
    d_preds[n] = bi;
}

// ---------------- launch 1: mask (inline idx-dtype detect) ----------------
__global__ __launch_bounds__(256) void mask_kernel(const float* __restrict__ coords,
                                                   const float* __restrict__ normz,
                                                   const void* __restrict__ nidx) {
    int n = blockIdx.x * 256 + threadIdx.x;
    if (n >= NN) return;
    const int* pw = (const int*)nidx;
    int is64 = 1;
#pragma unroll
    for (int k = 1; k < 40; k += 2) is64 &= (pw[k] == 0);

    int p = d_preds[n];
    const long long* ni64 = (const long long*)nidx;
    const int*       ni32 = (const int*)nidx;
    int cnt = 0;
#pragma unroll
    for (int k = 0; k < KK; k++) {
        long long raw = is64 ? ni64[(long long)n * KK + k]
                             : (long long)ni32[(long long)n * KK + k];
        unsigned int idx = (unsigned int)raw;
        if (idx >= NN) idx = 0;
        cnt += (d_preds[idx] == p);
    }
    bool cmask = cnt > 16;
    bool plane   = (p == 2) | (p == 3) | (p == 4);
    bool manmade = (p == 5);
    bool other   = (p == 0) | (p == 1) | (p == 6);
    float nz = normz[n];
    float z  = coords[(long long)n * 3 + 2];
    bool ground = plane && (nz > 0.9f) && (z < -10.0f);
    bool g = ground || other || manmade;
    bool m = (manmade && (nz < 0.1f)) || other || plane;
    d_maskf[n] = (cmask && g && m) ? 1.f : 0.f;
}

// ---------------- launch 2: feat_h = relu(feat @ W); fp32 + bf16 hi/lo (+masked) ----------------
__global__ __launch_bounds__(256) void feath_kernel(const float* __restrict__ feat,
                                                    const float* __restrict__ w) {
    __shared__ __align__(16) float As[32][68];
    __shared__ __align__(16) float Bs[32][68];
    __shared__ float sT[64][65];
    int tid = threadIdx.x;
    int h0 = blockIdx.x * 64;
    int n0 = blockIdx.y * 64;     // up to KPAD-64
    int tx = tid & 15, ty = tid >> 4;
    unsigned long long acc[4][2];
#pragma unroll
    for (int r = 0; r < 4; r++) { acc[r][0] = 0ull; acc[r][1] = 0ull; }

    for (int k0 = 0; k0 < DD; k0 += 32) {
        for (int i = tid; i < 64 * 32; i += 256) {
            int k = i & 31, m = i >> 5;
            int n = n0 + m;
            As[k][m] = (n < NN) ? feat[(long long)n * DD + k0 + k] : 0.f;
        }
        for (int i = tid; i < 32 * 64; i += 256) {
            int k = i >> 6, m = i & 63;
            Bs[k][m] = w[(k0 + k) * HH + h0 + m];
        }
        __syncthreads();
#pragma unroll
        for (int k = 0; k < 32; k++) {
            float4 a = *reinterpret_cast<const float4*>(&As[k][ty << 2]);
            double2 bd = *reinterpret_cast<const double2*>(&Bs[k][tx << 2]);
            unsigned long long b0 = d2u(bd.x), b1 = d2u(bd.y);
            unsigned long long a0 = dup2(a.x), a1 = dup2(a.y), a2 = dup2(a.z), a3 = dup2(a.w);
            acc[0][0] = ffma2(a0, b0, acc[0][0]); acc[0][1] = ffma2(a0, b1, acc[0][1]);
            acc[1][0] = ffma2(a1, b0, acc[1][0]); acc[1][1] = ffma2(a1, b1, acc[1][1]);
            acc[2][0] = ffma2(a2, b0, acc[2][0]); acc[2][1] = ffma2(a2, b1, acc[2][1]);
            acc[3][0] = ffma2(a3, b0, acc[3][0]); acc[3][1] = ffma2(a3, b1, acc[3][1]);
        }
        __syncthreads();
    }
    // relu, fp32 write, stage transpose
#pragma unroll
    for (int r = 0; r < 4; r++) {
        int n = n0 + (ty << 2) + r;
        float2 v0 = up2(acc[r][0]);
        float2 v1 = up2(acc[r][1]);
        float4 o = make_float4(fmaxf(v0.x, 0.f), fmaxf(v0.y, 0.f),
                               fmaxf(v1.x, 0.f), fmaxf(v1.y, 0.f));
        if (n < NN)
            *reinterpret_cast<float4*>(&d_featH[(long long)n * HH + h0 + (tx << 2)]) = o;
        sT[(tx << 2) + 0][(ty << 2) + r] = o.x;
        sT[(tx << 2) + 1][(ty << 2) + r] = o.y;
        sT[(tx << 2) + 2][(ty << 2) + r] = o.z;
        sT[(tx << 2) + 3][(ty << 2) + r] = o.w;
    }
    __syncthreads();
    // transposed bf16 hi/lo + masked variants: row = h, contiguous n
    int hrow = tid >> 2, q = tid & 3;
    size_t gb = (size_t)(h0 + hrow) * KPAD + n0 + q * 16;
    __align__(16) __nv_bfloat16 hb[16], lb[16], mhb[16], mlb[16];
    __nv_bfloat16 zero = __float2bfloat16(0.f);
#pragma unroll
    for (int i = 0; i < 16; i++) {
        int n = n0 + q * 16 + i;
        float v = sT[hrow][q * 16 + i];
        __nv_bfloat16 h = __float2bfloat16(v);
        hb[i] = h;
        lb[i] = __float2bfloat16(v - __bfloat162float(h));
        bool mk = (n < NN) && (d_maskf[n] != 0.f);
        mhb[i] = mk ? hb[i] : zero;
        mlb[i] = mk ? lb[i] : zero;
    }
    *reinterpret_cast<uint4*>(&d_FhThi[gb])      = *reinterpret_cast<uint4*>(&hb[0]);
    *reinterpret_cast<uint4*>(&d_FhThi[gb + 8])  = *reinterpret_cast<uint4*>(&hb[8]);
    *reinterpret_cast<uint4*>(&d_FhTlo[gb])      = *reinterpret_cast<uint4*>(&lb[0]);
    *reinterpret_cast<uint4*>(&d_FhTlo[gb + 8])  = *reinterpret_cast<uint4*>(&lb[8]);
    *reinterpret_cast<uint4*>(&d_FhThiM[gb])     = *reinterpret_cast<uint4*>(&mhb[0]);
    *reinterpret_cast<uint4*>(&d_FhThiM[gb + 8]) = *reinterpret_cast<uint4*>(&mhb[8]);
    *reinterpret_cast<uint4*>(&d_FhTloM[gb])     = *reinterpret_cast<uint4*>(&mlb[0]);
    *reinterpret_cast<uint4*>(&d_FhTloM[gb + 8]) = *reinterpret_cast<uint4*>(&mlb[8]);
}

// ---------------- launch 3: Gram via mma.sync bf16 hi/lo, split-K, cp.async 2-stage ----------------
__global__ __launch_bounds__(256, 1) void gram_hmma_kernel() {
    extern __shared__ __align__(16) char smg[];
    uint32_t sb = smem_to_u32(smg);
    int tid = threadIdx.x;
    int t = blockIdx.x, sp = blockIdx.y;
    int bi = 0;
    while ((bi + 1) * (bi + 2) / 2 <= t) bi++;
    int bj = t - bi * (bi + 1) / 2;
    int h10 = bi * 128, h20 = bj * 128;

    int lrow = tid >> 1, lhalf = tid & 1;
    size_t kstart = (size_t)sp * CPT * 64 + lhalf * 32;
    const __nv_bfloat16* sAh = d_FhThiM + (size_t)(h10 + lrow) * KPAD + kstart;
    const __nv_bfloat16* sAl = d_FhTloM + (size_t)(h10 + lrow) * KPAD + kstart;
    const __nv_bfloat16* sBh = d_FhThi  + (size_t)(h20 + lrow) * KPAD + kstart;
    const __nv_bfloat16* sBl = d_FhTlo  + (size_t)(h20 + lrow) * KPAD + kstart;
    uint32_t ldst = sb + lrow * GS_ROWB + lhalf * 64;

    int wid = tid >> 5, lane = tid & 31;
    int mbase = (wid >> 2) * 64, nbase = (wid & 3) * 32;
    int arow = (lane & 7) + ((lane >> 3) & 1) * 8;
    int acol = ((lane >> 4) & 1) * 8;
    int brow = (lane & 7) + ((lane >> 4) & 1) * 8;
    int bcol = ((lane >> 3) & 1) * 8;
    uint32_t aoff[4], boff[2];
#pragma unroll
    for (int mi = 0; mi < 4; mi++)
        aoff[mi] = (uint32_t)(((mbase + mi * 16 + arow) * 72 + acol) * 2);
#pragma unroll
    for (int nj = 0; nj < 2; nj++)
        boff[nj] = (uint32_t)(((nbase + nj * 16 + brow) * 72 + bcol) * 2);

    float acc[4][4][4];
#pragma unroll
    for (int a = 0; a < 4; a++)
#pragma unroll
        for (int b = 0; b < 4; b++)
#pragma unroll
            for (int c = 0; c < 4; c++) acc[a][b][c] = 0.f;

    {
        uint32_t base = ldst;
#pragma unroll
        for (int j = 0; j < 4; j++) {
            CP_ASYNC16(base + 0 * GS_TILE + j * 16, sAh + j * 8);
            CP_ASYNC16(base + 1 * GS_TILE + j * 16, sAl + j * 8);
            CP_ASYNC16(base + 2 * GS_TILE + j * 16, sBh + j * 8);
            CP_ASYNC16(base + 3 * GS_TILE + j * 16, sBl + j * 8);
        }
        CP_COMMIT();
    }

    for (int c = 0; c < CPT; c++) {
        if (c + 1 < CPT) {
            uint32_t base = ldst + ((c + 1) & 1) * GS_STAGE;
            size_t ko = (size_t)(c + 1) * 64;
#pragma unroll
            for (int j = 0; j < 4; j++) {
                CP_ASYNC16(base + 0 * GS_TILE + j * 16, sAh + ko + j * 8);
                CP_ASYNC16(base + 1 * GS_TILE + j * 16, sAl + ko + j * 8);
                CP_ASYNC16(base + 2 * GS_TILE + j * 16, sBh + ko + j * 8);
                CP_ASYNC16(base + 3 * GS_TILE + j * 16, sBl + ko + j * 8);
            }
            CP_COMMIT();
            CP_WAIT1();
        } else {
            CP_WAIT0();
        }
        __syncthreads();
        uint32_t stg = sb + (c & 1) * GS_STAGE;
#pragma unroll
        for (int ks = 0; ks < 4; ks++) {
            uint32_t kb = ks * 32;
            uint32_t ah[4][4], al[4][4], bh[4][2], bl[4][2];
#pragma unroll
            for (int mi = 0; mi < 4; mi++)
                LDSM4(ah[mi], stg + 0 * GS_TILE + aoff[mi] + kb);
#pragma unroll
            for (int nj = 0; nj < 2; nj++) {
                uint32_t r[4];
                LDSM4(r, stg + 2 * GS_TILE + boff[nj] + kb);
                bh[nj * 2][0] = r[0]; bh[nj * 2][1] = r[1];
                bh[nj * 2 + 1][0] = r[2]; bh[nj * 2 + 1][1] = r[3];
            }
#pragma unroll
            for (int mi = 0; mi < 4; mi++)
#pragma unroll
                for (int nj = 0; nj < 4; nj++) MMA16816(acc[mi][nj], ah[mi], bh[nj]);
#pragma unroll
            for (int nj = 0; nj < 2; nj++) {
                uint32_t r[4];
                LDSM4(r, stg + 3 * GS_TILE + boff[nj] + kb);
                bl[nj * 2][0] = r[0]; bl[nj * 2][1] = r[1];
                bl[nj * 2 + 1][0] = r[2]; bl[nj * 2 + 1][1] = r[3];
            }
#pragma unroll
            for (int mi = 0; mi < 4; mi++)
#pragma unroll
                for (int nj = 0; nj < 4; nj++) MMA16816(acc[mi][nj], ah[mi], bl[nj]);
#pragma unroll
            for (int mi = 0; mi < 4; mi++)
                LDSM4(al[mi], stg + 1 * GS_TILE + aoff[mi] + kb);
#pragma unroll
            for (int mi = 0; mi < 4; mi++)
#pragma unroll
                for (int nj = 0; nj < 4; nj++) MMA16816(acc[mi][nj], al[mi], bh[nj]);
        }
        __syncthreads();
    }

    float* out = &d_Spart[(size_t)(sp * NTRI + t) * 128 * 128];
    int g = lane >> 2, q = lane & 3;
#pragma unroll
    for (int mi = 0; mi < 4; mi++) {
#pragma unroll
        for (int nj = 0; nj < 4; nj++) {
            int r0 = mbase + mi * 16 + g;
            int cc = nbase + nj * 8 + q * 2;
            *reinterpret_cast<float2*>(&out[r0 * 128 + cc]) =
                make_float2(acc[mi][nj][0], acc[mi][nj][1]);
            *reinterpret_cast<float2*>(&out[(r0 + 8) * 128 + cc]) =
                make_float2(acc[mi][nj][2], acc[mi][nj][3]);
        }
    }
}

// ---------------- reduce split-K partials into d_Gn lower triangle ----------------
__global__ __launch_bounds__(256) void greduce_kernel() {
    int t = blockIdx.x;
    int bi = 0;
    while ((bi + 1) * (bi + 2) / 2 <= t) bi++;
    int bj = t - bi * (bi + 1) / 2;
    for (int i = threadIdx.x; i < 128 * 128 / 4; i += 256) {
        float4 s = make_float4(0.f, 0.f, 0.f, 0.f);
#pragma unroll
        for (int sp = 0; sp < GSPLIT; sp++) {
            float4 v = *reinterpret_cast<const float4*>(
                &d_Spart[(size_t)(sp * NTRI + t) * 128 * 128 + i * 4]);
            s.x += v.x; s.y += v.y; s.z += v.z; s.w += v.w;
        }
        int r = (i * 4) >> 7, c = (i * 4) & 127;
        *reinterpret_cast<float4*>(&d_Gn[(bi * 128 + r) * HH + bj * 128 + c]) = s;
    }
}

// ---------------- Qn partials ----------------
__global__ __launch_bounds__(256) void qpart_kernel() {
    int h = blockIdx.x * 256 + threadIdx.x;
    int chunk = blockIdx.y;
    int nb = chunk * NPER;
    float a0 = 0, a1 = 0, a2 = 0, a3 = 0, a4 = 0, a5 = 0, a6 = 0;
    for (int t = 0; t < NPER; t++) {
        int n = nb + t;
        float mv = d_maskf[n];
        if (mv != 0.f) {
            float v = d_featH[(long long)n * HH + h];
            int p = d_preds[n];
            a0 += (p == 0) ? v : 0.f;
            a1 += (p == 1) ? v : 0.f;
            a2 += (p == 2) ? v : 0.f;
            a3 += (p == 3) ? v : 0.f;
            a4 += (p == 4) ? v : 0.f;
            a5 += (p == 5) ? v : 0.f;
            a6 += (p == 6) ? v : 0.f;
        }
    }
    int o = (chunk * HH + h) * CC;
    d_Qpart[o + 0] = a0; d_Qpart[o + 1] = a1; d_Qpart[o + 2] = a2; d_Qpart[o + 3] = a3;
    d_Qpart[o + 4] = a4; d_Qpart[o + 5] = a5; d_Qpart[o + 6] = a6;
}

__global__ void qreduce_kernel(const float* __restrict__ Qin) {
    int idx = blockIdx.x * 256 + threadIdx.x;
    if (idx >= HH * CC) return;
    float s = Qin[idx];
    for (int ch = 0; ch < NCHUNK; ch++) s += d_Qpart[ch * HH * CC + idx];
    d_Qn[idx] = s;
}

// ---------------- mirror + Gin + ridge -> fp32 A (two copies) ----------------
__global__ void convm_kernel(const float* __restrict__ Gin) {
    int idx = blockIdx.x * 256 + threadIdx.x;
    int i = idx >> 10, j = idx & 1023;
    float v = (i >= j) ? d_Gn[i * HH + j] : d_Gn[j * HH + i];
    float a = v + Gin[idx] + ((i == j) ? 100.0f : 0.0f);
    d_GA[idx] = a;
    d_Gf[idx] = a;
}

// ---------------- blocked fp32 Cholesky (lower), block = 64 ----------------
__global__ void chol_potf2(int kb) {
    int i = threadIdx.x;
    int off = kb * 64;
    __shared__ float s[64][65];
    for (int j = 0; j < 64; j++) s[i][j] = d_Gf[(off + i) * HH + off + j];
    __syncthreads();
    for (int j = 0; j < 64; j++) {
        if (i == j) s[j][j] = sqrtf(fmaxf(s[j][j], 1e-20f));
        __syncthreads();
        if (i > j) s[i][j] /= s[j][j];
        __syncthreads();
        if (i > j) {
            float lij = s[i][j];
            for (int k = j + 1; k <= i; k++) s[i][k] -= lij * s[k][j];
        }
        __syncthreads();
    }
    for (int j = 0; j <= i; j++) d_Gf[(off + i) * HH + off + j] = s[i][j];
    d_dinvf[off + i] = 1.0f / s[i][i];
}

__global__ __launch_bounds__(128) void chol_trsm(int kb) {
    int off = kb * 64;
    int base = off + 64;
    __shared__ float L[64][65];
    __shared__ float di[64];
    for (int i = threadIdx.x; i < 64 * 64; i += 128)
        L[i >> 6][i & 63] = d_Gf[(off + (i >> 6)) * HH + off + (i & 63)];
    if (threadIdx.x < 64) di[threadIdx.x] = d_dinvf[off + threadIdx.x];
    __syncthreads();
    int r = base + blockIdx.x * 128 + threadIdx.x;
    if (r >= HH) return;
    float* a = &d_Gf[r * HH + off];
    float x[64];
#pragma unroll
    for (int j = 0; j < 64; j++) x[j] = a[j];
#pragma unroll
    for (int j = 0; j < 64; j++) {
        float xj = x[j] * di[j];
        x[j] = xj;
#pragma unroll
        for (int tt = j + 1; tt < 64; tt++) x[tt] -= xj * L[tt][j];
    }
#pragma unroll
    for (int j = 0; j < 64; j++) a[j] = x[j];
}

__global__ __launch_bounds__(256) void chol_syrk(int kb) {
    int off = kb * 64;
    int base = off + 64;
    int i0 = base + blockIdx.y * 32;
    int j0 = base + blockIdx.x * 32;
    if (j0 > i0) return;
    __shared__ float Li[32][65];
    __shared__ float Lj[32][65];
    int tid = threadIdx.x;
    for (int i = tid; i < 32 * 64; i += 256) {
        int ii = i >> 6, t = i & 63;
        Li[ii][t] = d_Gf[(i0 + ii) * HH + off + t];
        Lj[ii][t] = d_Gf[(j0 + ii) * HH + off + t];
    }
    __syncthreads();
    int tx = tid & 31, ty = tid >> 5;
    float acc[4] = {0, 0, 0, 0};
    for (int t = 0; t < 64; t++) {
        float bj = Lj[tx][t];
#pragma unroll
        for (int r = 0; r < 4; r++) acc[r] += Li[(ty << 2) + r][t] * bj;
    }
#pragma unroll
    for (int r = 0; r < 4; r++) {
        int i = i0 + (ty << 2) + r;
        int j = j0 + tx;
        if (j <= i) d_Gf[i * HH + j] -= acc[r];
    }
}

// ---------------- triangular solves: L y = b ; L^T x = y (7 RHS); mode 0: x=wo(=), 1: wo+=x, b=res ----------------
__global__ __launch_bounds__(1024) void chol_solve(int mode) {
    int i = threadIdx.x;
    __shared__ float shy[64][CC];
    float y[CC];
    const float* b = (mode == 0) ? d_Qn : d_res;
#pragma unroll
    for (int c = 0; c < CC; c++) y[c] = b[i * CC + c];
    for (int jb = 0; jb < HH; jb += 64) {
        for (int j = jb; j < jb + 64; j++) {
            if (i == j) {
                float dgl = d_dinvf[j];
#pragma unroll
                for (int c = 0; c < CC; c++) { y[c] *= dgl; shy[j - jb][c] = y[c]; }
            }
            __syncthreads();
            if (i > j && i < jb + 64) {
                float lij = d_Gf[i * HH + j];
#pragma unroll
                for (int c = 0; c < CC; c++) y[c] -= lij * shy[j - jb][c];
            }
            __syncthreads();
        }
        if (i >= jb + 64) {
            for (int t = 0; t < 64; t++) {
                float lij = d_Gf[i * HH + jb + t];
#pragma unroll
                for (int c = 0; c < CC; c++) y[c] -= lij * shy[t][c];
            }
        }
        __syncthreads();
    }
    for (int jb = HH - 64; jb >= 0; jb -= 64) {
        for (int j = jb + 63; j >= jb; j--) {
            if (i == j) {
                float dgl = d_dinvf[j];
#pragma unroll
                for (int c = 0; c < CC; c++) { y[c] *= dgl; shy[j - jb][c] = y[c]; }
            }
            __syncthreads();
            if (i >= jb && i < j) {
                float lji = d_Gf[j * HH + i];
#pragma unroll
                for (int c = 0; c < CC; c++) y[c] -= lji * shy[j - jb][c];
            }
            __syncthreads();
        }
        if (i < jb) {
            for (int t = 0; t < 64; t++) {
                float lji = d_Gf[(jb + t) * HH + i];
#pragma unroll
                for (int c = 0; c < CC; c++) y[c] -= lji * shy[t][c];
            }
        }
        __syncthreads();
    }
    if (mode == 0) {
#pragma unroll
        for (int c = 0; c < CC; c++) d_wo[i * CC + c] = y[c];
    } else {
#pragma unroll
        for (int c = 0; c < CC; c++) d_wo[i * CC + c] += y[c];
    }
}

// ---------------- residual r = Qn - A*wo, fp32 TwoProd + Neumaier compensation ----------------
__global__ __launch_bounds__(256) void resid_kernel() {
    __shared__ float sw[HH * CC];
    int tid = threadIdx.x;
    for (int i = tid; i < HH * CC; i += 256) sw[i] = d_wo[i];
    __syncthreads();
    int wid = tid >> 5, lane = tid & 31;
    int row = blockIdx.x * 8 + wid;
    float s[CC], comp[CC];
#pragma unroll
    for (int c = 0; c < CC; c++) {
        s[c] = (lane == 0) ? d_Qn[row * CC + c] : 0.f;
        comp[c] = 0.f;
    }
    const float* arow = &d_GA[row * HH];
    for (int j = lane; j < HH; j += 32) {
        float na = -arow[j];
#pragma unroll
        for (int c = 0; c < CC; c++) {
            float w = sw[j * CC + c];
            float p = na * w;
            float e = fmaf(na, w, -p);          // exact product tail
            float t = s[c] + p;                 // TwoSum
            float bb = t - s[c];
            float err = (s[c] - (t - bb)) + (p - bb);
            s[c] = t;
            comp[c] += err + e;
        }
    }
#pragma unroll
    for (int c = 0; c < CC; c++) {
#pragma unroll
        for (int off = 16; off > 0; off >>= 1) {
            float s2 = __shfl_xor_sync(0xffffffffu, s[c], off);
            float c2 = __shfl_xor_sync(0xffffffffu, comp[c], off);
            float t = s[c] + s2;                // TwoSum merge
            float bb = t - s[c];
            float err = (s[c] - (t - bb)) + (s2 - bb);
            s[c] = t;
            comp[c] += c2 + err;
        }
    }
    if (lane == 0) {
#pragma unroll
        for (int c = 0; c < CC; c++) d_res[row * CC + c] = s[c] + comp[c];
    }
}

// ---------------- pred_domain = featH @ wo ----------------
__global__ __launch_bounds__(256) void final_kernel(float* __restrict__ out) {
    __shared__ float sw[HH * CC];
    int tid = threadIdx.x;
    for (int i = tid; i < HH * CC; i += 256) sw[i] = d_wo[i];
    __syncthreads();
    int warp = tid >> 5, lane = tid & 31;
    int n = blockIdx.x * 8 + warp;
    if (n >= NN) return;
    const float* a = &d_featH[(long long)n * HH];
    float acc[CC];
#pragma unroll
    for (int c = 0; c < CC; c++) acc[c] = 0.f;
    for (int h = lane; h < HH; h += 32) {
        float v = a[h];
#pragma unroll
        for (int c = 0; c < CC; c++) acc[c] += v * sw[h * CC + c];
    }
#pragma unroll
    for (int c = 0; c < CC; c++) {
#pragma unroll
        for (int off = 16; off > 0; off >>= 1)
            acc[c] += __shfl_xor_sync(0xffffffffu, acc[c], off);
    }
    if (lane == 0) {
#pragma unroll
        for (int c = 0; c < CC; c++) out[(long long)n * CC + c] = acc[c];
    }
}

// ---------------- launcher ----------------
extern "C" void kernel_launch(void* const* d_in, const int* in_sizes, int n_in,
                              void* d_out, int out_size) {
    const float* feat   = (const float*)d_in[0];
    const float* proto  = (const float*)d_in[1];
    const float* wrand  = (const float*)d_in[2];
    const float* Qin    = (const float*)d_in[3];
    const float* Gin    = (const float*)d_in[4];
    const float* coords = (const float*)d_in[5];
    const float* normz  = (const float*)d_in[6];
    const void*  nidx   = (const void*)d_in[7];
    float* out = (float*)d_out;

    cudaFuncSetAttribute(gram_hmma_kernel,
                         cudaFuncAttributeMaxDynamicSharedMemorySize, GS_TOTAL);

    preds_kernel<<<(NN + 255) / 256, 256>>>(feat, proto);                 // 0
    mask_kernel<<<(NN + 255) / 256, 256>>>(coords, normz, nidx);          // 1
    feath_kernel<<<dim3(HH / 64, KPAD / 64), 256>>>(feat, wrand);         // 2
    gram_hmma_kernel<<<dim3(NTRI, GSPLIT), 256, GS_TOTAL>>>();            // 3 <- ncu slot
    greduce_kernel<<<NTRI, 256>>>();                                      // 4
    qpart_kernel<<<dim3(HH / 256, NCHUNK), 256>>>();
    qreduce_kernel<<<(HH * CC + 255) / 256, 256>>>(Qin);
    convm_kernel<<<(HH * HH) / 256, 256>>>(Gin);

    for (int kb = 0; kb < HH / 64; kb++) {
        chol_potf2<<<1, 64>>>(kb);
        int rows = HH - (kb * 64 + 64);
        if (rows > 0) {
            chol_trsm<<<(rows + 127) / 128, 128>>>(kb);
            int nt = (rows + 31) / 32;
            chol_syrk<<<dim3(nt, nt), 256>>>(kb);
        }
    }
    chol_solve<<<1, 1024>>>(0);
    resid_kernel<<<HH / 8, 256>>>();
    chol_solve<<<1, 1024>>>(1);
    resid_kernel<<<HH / 8, 256>>>();
    chol_solve<<<1, 1024>>>(1);
    final_kernel<<<(NN + 7) / 8, 256>>>(out);
}

// round 11
// speedup vs baseline: 4.8952x; 1.0233x over previous
#include <cuda_runtime.h>
#include <cuda_bf16.h>
#include <math.h>
#include <stdint.h>

#define NN 100000
#define KK 20
#define DD 96
#define HH 1024
#define CC 7
#define KPAD 100096               // 1564 * 64
#define NCHK (KPAD / 64)          // 1564
#define GSPLIT 4
#define CPT (NCHK / GSPLIT)       // 391 k-chunks per split
#define NTRI 36
#define NCHUNK 32
#define NPER (NN / NCHUNK)        // 3125

// gram smem geometry: 4 tiles of 128 rows x 72 bf16 (64 used + 8 pad), double buffered
#define GS_ROWB 144               // bytes per padded row
#define GS_TILE (128 * GS_ROWB)   // 18432 B
#define GS_STAGE (4 * GS_TILE)    // 73728 B
#define GS_TOTAL (2 * GS_STAGE)   // 147456 B

// ---------------- scratch (static device globals; no allocations) ----------------
static __device__ int           d_preds[NN];
static __device__ float         d_maskf[NN];
static __device__ float         d_featH[(long long)NN * HH];        // 400 MB fp32
static __device__ __nv_bfloat16 d_Fhi[(long long)HH * KPAD];        // masked transposed hi
static __device__ __nv_bfloat16 d_Flo[(long long)HH * KPAD];        // masked transposed lo
static __device__ float         d_Spart[GSPLIT * NTRI * 128 * 128]; // split-K partials
static __device__ float         d_Qpart[NCHUNK * HH * CC];
static __device__ float         d_Qn[HH * CC];
static __device__ float         d_Gn[HH * HH];
static __device__ float         d_GA[HH * HH];   // A = G + Gin + ridge (kept for IR)
static __device__ float         d_Gf[HH * HH];   // factored in place (fp32 Cholesky)
static __device__ float         d_dinvf[HH];
static __device__ float         d_res[HH * CC];
static __device__ float         d_wo[HH * CC];

// ---------------- ptx helpers (base-target features only: sm_80+) ----------------
__device__ __forceinline__ uint32_t smem_to_u32(const void* smem_ptr) {
    uint32_t addr;
    asm("{ .reg .u64 tmp; cvta.to.shared.u64 tmp, %1; cvt.u32.u64 %0, tmp; }"
        : "=r"(addr) : "l"(smem_ptr));
    return addr;
}
#define CP_ASYNC16(dst, src) \
    asm volatile("cp.async.cg.shared.global [%0], [%1], 16;" :: "r"(dst), "l"(src))
#define CP_COMMIT() asm volatile("cp.async.commit_group;" ::: "memory")
#define CP_WAIT1()  asm volatile("cp.async.wait_group 1;" ::: "memory")
#define CP_WAIT0()  asm volatile("cp.async.wait_group 0;" ::: "memory")
#define LDSM4(r, addr) \
    asm volatile("ldmatrix.sync.aligned.m8n8.x4.shared.b16 {%0,%1,%2,%3}, [%4];" \
        : "=r"((r)[0]), "=r"((r)[1]), "=r"((r)[2]), "=r"((r)[3]) : "r"(addr))
#define MMA16816(c, a, b) \
    asm volatile("mma.sync.aligned.m16n8k16.row.col.f32.bf16.bf16.f32 " \
        "{%0,%1,%2,%3}, {%4,%5,%6,%7}, {%8,%9}, {%0,%1,%2,%3};" \
        : "+f"((c)[0]), "+f"((c)[1]), "+f"((c)[2]), "+f"((c)[3]) \
        : "r"((a)[0]), "r"((a)[1]), "r"((a)[2]), "r"((a)[3]), "r"((b)[0]), "r"((b)[1]))

// ---------------- f32x2 helpers (feath) ----------------
__device__ __forceinline__ unsigned long long ffma2(unsigned long long a,
                                                    unsigned long long b,
                                                    unsigned long long c) {
    unsigned long long d;
    asm("fma.rn.f32x2 %0, %1, %2, %3;" : "=l"(d) : "l"(a), "l"(b), "l"(c));
    return d;
}
__device__ __forceinline__ unsigned long long dup2(float x) {
    unsigned long long d;
    asm("mov.b64 %0, {%1, %1};" : "=l"(d) : "f"(x));
    return d;
}
__device__ __forceinline__ float2 up2(unsigned long long v) {
    float2 r;
    asm("mov.b64 {%0, %1}, %2;" : "=f"(r.x), "=f"(r.y) : "l"(v));
    return r;
}
__device__ __forceinline__ unsigned long long d2u(double d) {
    return (unsigned long long)__double_as_longlong(d);
}

// ---------------- no-op (shifts ncu capture slot onto feath) ----------------
__global__ void dummy_kernel() {}

// ---------------- launch 0: preds (with inline proto normalize) ----------------
__global__ __launch_bounds__(256) void preds_kernel(const float* __restrict__ feat,
                                                    const float* __restrict__ proto) {
    __shared__ float sp[CC][DD];
    int tid = threadIdx.x;
    if (tid < CC) {
        float s = 0.f;
        for (int k = 0; k < DD; k++) { float v = proto[tid * DD + k]; s += v * v; }
        float inv = 1.f / fmaxf(sqrtf(s), 1e-12f);
        for (int k = 0; k < DD; k++) sp[tid][k] = proto[tid * DD + k] * inv;
    }
    __syncthreads();
    int n = blockIdx.x * 256 + tid;
    if (n >= NN) return;
    const float* f = feat + (long long)n * DD;
    float acc[CC];
#pragma unroll
    for (int c = 0; c < CC; c++) acc[c] = 0.f;
    for (int k = 0; k < DD; k++) {
        float fk = f[k];
#pragma unroll
        for (int c = 0; c < CC; c++) acc[c] += fk * sp[c][k];
    }
    float best = acc[0];
    int bi = 0;
#pragma unroll
    for (int c = 1; c < CC; c++)
        if (acc[c] > best) { best = acc[c]; bi = c; }
    d_preds[n] = bi;
}

// ---------------- launch 1: mask (inline idx-dtype detect) ----------------
__global__ __launch_bounds__(256) void mask_kernel(const float* __restrict__ coords,
                                                   const float* __restrict__ normz,
                                                   const void* __restrict__ nidx) {
    int n = blockIdx.x * 256 + threadIdx.x;
    if (n >= NN) return;
    const int* pw = (const int*)nidx;
    int is64 = 1;
#pragma unroll
    for (int k = 1; k < 40; k += 2) is64 &= (pw[k] == 0);

    int p = d_preds[n];
    const long long* ni64 = (const long long*)nidx;
    const int*       ni32 = (const int*)nidx;
    int cnt = 0;
#pragma unroll
    for (int k = 0; k < KK; k++) {
        long long raw = is64 ? ni64[(long long)n * KK + k]
                             : (long long)ni32[(long long)n * KK + k];
        unsigned int idx = (unsigned int)raw;
        if (idx >= NN) idx = 0;
        cnt += (d_preds[idx] == p);
    }
    bool cmask = cnt > 16;
    bool plane   = (p == 2) | (p == 3) | (p == 4);
    bool manmade = (p == 5);
    bool other   = (p == 0) | (p == 1) | (p == 6);
    float nz = normz[n];
    float z  = coords[(long long)n * 3 + 2];
    bool ground = plane && (nz > 0.9f) && (z < -10.0f);
    bool g = ground || other || manmade;
    bool m = (manmade && (nz < 0.1f)) || other || plane;
    d_maskf[n] = (cmask && g && m) ? 1.f : 0.f;
}

// ---------------- launch 3 (ncu slot): feat_h = relu(feat @ W); fp32 + masked bf16 hi/lo ----------------
__global__ __launch_bounds__(256) void feath_kernel(const float* __restrict__ feat,
                                                    const float* __restrict__ w) {
    __shared__ __align__(16) float As[32][68];
    __shared__ __align__(16) float Bs[32][68];
    __shared__ float sT[64][65];
    int tid = threadIdx.x;
    int h0 = blockIdx.x * 64;
    int n0 = blockIdx.y * 64;     // up to KPAD-64
    int tx = tid & 15, ty = tid >> 4;
    unsigned long long acc[4][2];
#pragma unroll
    for (int r = 0; r < 4; r++) { acc[r][0] = 0ull; acc[r][1] = 0ull; }

    for (int k0 = 0; k0 < DD; k0 += 32) {
        for (int i = tid; i < 64 * 32; i += 256) {
            int k = i & 31, m = i >> 5;
            int n = n0 + m;
            As[k][m] = (n < NN) ? feat[(long long)n * DD + k0 + k] : 0.f;
        }
        for (int i = tid; i < 32 * 64; i += 256) {
            int k = i >> 6, m = i & 63;
            Bs[k][m] = w[(k0 + k) * HH + h0 + m];
        }
        __syncthreads();
#pragma unroll
        for (int k = 0; k < 32; k++) {
            float4 a = *reinterpret_cast<const float4*>(&As[k][ty << 2]);
            double2 bd = *reinterpret_cast<const double2*>(&Bs[k][tx << 2]);
            unsigned long long b0 = d2u(bd.x), b1 = d2u(bd.y);
            unsigned long long a0 = dup2(a.x), a1 = dup2(a.y), a2 = dup2(a.z), a3 = dup2(a.w);
            acc[0][0] = ffma2(a0, b0, acc[0][0]); acc[0][1] = ffma2(a0, b1, acc[0][1]);
            acc[1][0] = ffma2(a1, b0, acc[1][0]); acc[1][1] = ffma2(a1, b1, acc[1][1]);
            acc[2][0] = ffma2(a2, b0, acc[2][0]); acc[2][1] = ffma2(a2, b1, acc[2][1]);
            acc[3][0] = ffma2(a3, b0, acc[3][0]); acc[3][1] = ffma2(a3, b1, acc[3][1]);
        }
        __syncthreads();
    }
    // relu, fp32 write, stage transpose
#pragma unroll
    for (int r = 0; r < 4; r++) {
        int n = n0 + (ty << 2) + r;
        float2 v0 = up2(acc[r][0]);
        float2 v1 = up2(acc[r][1]);
        float4 o = make_float4(fmaxf(v0.x, 0.f), fmaxf(v0.y, 0.f),
                               fmaxf(v1.x, 0.f), fmaxf(v1.y, 0.f));
        if (n < NN)
            *reinterpret_cast<float4*>(&d_featH[(long long)n * HH + h0 + (tx << 2)]) = o;
        sT[(tx << 2) + 0][(ty << 2) + r] = o.x;
        sT[(tx << 2) + 1][(ty << 2) + r] = o.y;
        sT[(tx << 2) + 2][(ty << 2) + r] = o.z;
        sT[(tx << 2) + 3][(ty << 2) + r] = o.w;
    }
    __syncthreads();
    // masked transposed bf16 hi/lo writes (mask^2 == mask => both gram sides masked)
    int hrow = tid >> 2, q = tid & 3;
    size_t gb = (size_t)(h0 + hrow) * KPAD + n0 + q * 16;
    __align__(16) __nv_bfloat16 mhb[16], mlb[16];
    __nv_bfloat16 zero = __float2bfloat16(0.f);
#pragma unroll
    for (int i = 0; i < 16; i++) {
        int n = n0 + q * 16 + i;
        bool mk = (n < NN) && (d_maskf[n] != 0.f);
        float v = sT[hrow][q * 16 + i];
        __nv_bfloat16 h = __float2bfloat16(v);
        mhb[i] = mk ? h : zero;
        mlb[i] = mk ? __float2bfloat16(v - __bfloat162float(h)) : zero;
    }
    *reinterpret_cast<uint4*>(&d_Fhi[gb])     = *reinterpret_cast<uint4*>(&mhb[0]);
    *reinterpret_cast<uint4*>(&d_Fhi[gb + 8]) = *reinterpret_cast<uint4*>(&mhb[8]);
    *reinterpret_cast<uint4*>(&d_Flo[gb])     = *reinterpret_cast<uint4*>(&mlb[0]);
    *reinterpret_cast<uint4*>(&d_Flo[gb + 8]) = *reinterpret_cast<uint4*>(&mlb[8]);
}

// ---------------- Gram via mma.sync bf16 hi/lo, split-K, cp.async 2-stage; 512 thr ----------------
__global__ __launch_bounds__(512, 1) void gram_hmma_kernel() {
    extern __shared__ __align__(16) char smg[];
    uint32_t sb = smem_to_u32(smg);
    int tid = threadIdx.x;
    int t = blockIdx.x, sp = blockIdx.y;
    int bi = 0;
    while ((bi + 1) * (bi + 2) / 2 <= t) bi++;
    int bj = t - bi * (bi + 1) / 2;
    int h10 = bi * 128, h20 = bj * 128;

    // loader mapping: 4 threads per row, each 2x cp.async 16B per tile
    int lrow = tid >> 2, lseg = tid & 3;
    size_t kstart = (size_t)sp * CPT * 64 + lseg * 16;
    const __nv_bfloat16* pAh = d_Fhi + (size_t)(h10 + lrow) * KPAD + kstart;
    const __nv_bfloat16* pAl = d_Flo + (size_t)(h10 + lrow) * KPAD + kstart;
    const __nv_bfloat16* pBh = d_Fhi + (size_t)(h20 + lrow) * KPAD + kstart;
    const __nv_bfloat16* pBl = d_Flo + (size_t)(h20 + lrow) * KPAD + kstart;
    uint32_t ldst = sb + lrow * GS_ROWB + lseg * 32;

    // compute mapping: 16 warps = 4 (M) x 4 (N); warp tile 32x32
    int wid = tid >> 5, lane = tid & 31;
    int mbase = (wid >> 2) * 32, nbase = (wid & 3) * 32;
    int arow = (lane & 7) + ((lane >> 3) & 1) * 8;
    int acol = ((lane >> 4) & 1) * 8;
    int brow = (lane & 7) + ((lane >> 4) & 1) * 8;
    int bcol = ((lane >> 3) & 1) * 8;
    uint32_t aoff[2], boff[2];
#pragma unroll
    for (int mi = 0; mi < 2; mi++)
        aoff[mi] = (uint32_t)(((mbase + mi * 16 + arow) * 72 + acol) * 2);
#pragma unroll
    for (int nj = 0; nj < 2; nj++)
        boff[nj] = (uint32_t)(((nbase + nj * 16 + brow) * 72 + bcol) * 2);

    float acc[2][4][4];
#pragma unroll
    for (int a = 0; a < 2; a++)
#pragma unroll
        for (int b = 0; b < 4; b++)
#pragma unroll
            for (int c = 0; c < 4; c++) acc[a][b][c] = 0.f;

    // prologue: stage 0
    {
        uint32_t base = ldst;
#pragma unroll
        for (int j = 0; j < 2; j++) {
            CP_ASYNC16(base + 0 * GS_TILE + j * 16, pAh + j * 8);
            CP_ASYNC16(base + 1 * GS_TILE + j * 16, pAl + j * 8);
            CP_ASYNC16(base + 2 * GS_TILE + j * 16, pBh + j * 8);
            CP_ASYNC16(base + 3 * GS_TILE + j * 16, pBl + j * 8);
        }
        CP_COMMIT();
    }

    for (int c = 0; c < CPT; c++) {
        if (c + 1 < CPT) {
            uint32_t base = ldst + ((c + 1) & 1) * GS_STAGE;
            size_t ko = (size_t)(c + 1) * 64;
#pragma unroll
            for (int j = 0; j < 2; j++) {
                CP_ASYNC16(base + 0 * GS_TILE + j * 16, pAh + ko + j * 8);
                CP_ASYNC16(base + 1 * GS_TILE + j * 16, pAl + ko + j * 8);
                CP_ASYNC16(base + 2 * GS_TILE + j * 16, pBh + ko + j * 8);
                CP_ASYNC16(base + 3 * GS_TILE + j * 16, pBl + ko + j * 8);
            }
            CP_COMMIT();
            CP_WAIT1();
        } else {
            CP_WAIT0();
        }
        __syncthreads();
        uint32_t stg = sb + (c & 1) * GS_STAGE;
#pragma unroll
        for (int ks = 0; ks < 4; ks++) {
            uint32_t kb = ks * 32;
            uint32_t ah[2][4], al[2][4], bh[4][2], bl[4][2];
#pragma unroll
            for (int mi = 0; mi < 2; mi++)
                LDSM4(ah[mi], stg + 0 * GS_TILE + aoff[mi] + kb);
#pragma unroll
            for (int nj = 0; nj < 2; nj++) {
                uint32_t r[4];
                LDSM4(r, stg + 2 * GS_TILE + boff[nj] + kb);
                bh[nj * 2][0] = r[0]; bh[nj * 2][1] = r[1];
                bh[nj * 2 + 1][0] = r[2]; bh[nj * 2 + 1][1] = r[3];
            }
#pragma unroll
            for (int mi = 0; mi < 2; mi++)
#pragma unroll
                for (int nj = 0; nj < 4; nj++) MMA16816(acc[mi][nj], ah[mi], bh[nj]);
#pragma unroll
            for (int nj = 0; nj < 2; nj++) {
                uint32_t r[4];
                LDSM4(r, stg + 3 * GS_TILE + boff[nj] + kb);
                bl[nj * 2][0] = r[0]; bl[nj * 2][1] = r[1];
                bl[nj * 2 + 1][0] = r[2]; bl[nj * 2 + 1][1] = r[3];
            }
#pragma unroll
            for (int mi = 0; mi < 2; mi++)
#pragma unroll
                for (int nj = 0; nj < 4; nj++) MMA16816(acc[mi][nj], ah[mi], bl[nj]);
#pragma unroll
            for (int mi = 0; mi < 2; mi++)
                LDSM4(al[mi], stg + 1 * GS_TILE + aoff[mi] + kb);
#pragma unroll
            for (int mi = 0; mi < 2; mi++)
#pragma unroll
                for (int nj = 0; nj < 4; nj++) MMA16816(acc[mi][nj], al[mi], bh[nj]);
        }
        __syncthreads();
    }

    // write 128x128 partial tile
    float* out = &d_Spart[(size_t)(sp * NTRI + t) * 128 * 128];
    int g = lane >> 2, q = lane & 3;
#pragma unroll
    for (int mi = 0; mi < 2; mi++) {
#pragma unroll
        for (int nj = 0; nj < 4; nj++) {
            int r0 = mbase + mi * 16 + g;
            int cc = nbase + nj * 8 + q * 2;
            *reinterpret_cast<float2*>(&out[r0 * 128 + cc]) =
                make_float2(acc[mi][nj][0], acc[mi][nj][1]);
            *reinterpret_cast<float2*>(&out[(r0 + 8) * 128 + cc]) =
                make_float2(acc[mi][nj][2], acc[mi][nj][3]);
        }
    }
}

// ---------------- reduce split-K partials into d_Gn lower triangle ----------------
__global__ __launch_bounds__(256) void greduce_kernel() {
    int t = blockIdx.x;
    int bi = 0;
    while ((bi + 1) * (bi + 2) / 2 <= t) bi++;
    int bj = t - bi * (bi + 1) / 2;
    for (int i = threadIdx.x; i < 128 * 128 / 4; i += 256) {
        float4 s = make_float4(0.f, 0.f, 0.f, 0.f);
#pragma unroll
        for (int sp = 0; sp < GSPLIT; sp++) {
            float4 v = *reinterpret_cast<const float4*>(
                &d_Spart[(size_t)(sp * NTRI + t) * 128 * 128 + i * 4]);
            s.x += v.x; s.y += v.y; s.z += v.z; s.w += v.w;
        }
        int r = (i * 4) >> 7, c = (i * 4) & 127;
        *reinterpret_cast<float4*>(&d_Gn[(bi * 128 + r) * HH + bj * 128 + c]) = s;
    }
}

// ---------------- Qn partials ----------------
__global__ __launch_bounds__(256) void qpart_kernel() {
    int h = blockIdx.x * 256 + threadIdx.x;
    int chunk = blockIdx.y;
    int nb = chunk * NPER;
    float a0 = 0, a1 = 0, a2 = 0, a3 = 0, a4 = 0, a5 = 0, a6 = 0;
    for (int t = 0; t < NPER; t++) {
        int n = nb + t;
        float mv = d_maskf[n];
        if (mv != 0.f) {
            float v = d_featH[(long long)n * HH + h];
            int p = d_preds[n];
            a0 += (p == 0) ? v : 0.f;
            a1 += (p == 1) ? v : 0.f;
            a2 += (p == 2) ? v : 0.f;
            a3 += (p == 3) ? v : 0.f;
            a4 += (p == 4) ? v : 0.f;
            a5 += (p == 5) ? v : 0.f;
            a6 += (p == 6) ? v : 0.f;
        }
    }
    int o = (chunk * HH + h) * CC;
    d_Qpart[o + 0] = a0; d_Qpart[o + 1] = a1; d_Qpart[o + 2] = a2; d_Qpart[o + 3] = a3;
    d_Qpart[o + 4] = a4; d_Qpart[o + 5] = a5; d_Qpart[o + 6] = a6;
}

__global__ void qreduce_kernel(const float* __restrict__ Qin) {
    int idx = blockIdx.x * 256 + threadIdx.x;
    if (idx >= HH * CC) return;
    float s = Qin[idx];
    for (int ch = 0; ch < NCHUNK; ch++) s += d_Qpart[ch * HH * CC + idx];
    d_Qn[idx] = s;
}

// ---------------- mirror + Gin + ridge -> fp32 A (two copies) ----------------
__global__ void convm_kernel(const float* __restrict__ Gin) {
    int idx = blockIdx.x * 256 + threadIdx.x;
    int i = idx >> 10, j = idx & 1023;
    float v = (i >= j) ? d_Gn[i * HH + j] : d_Gn[j * HH + i];
    float a = v + Gin[idx] + ((i == j) ? 100.0f : 0.0f);
    d_GA[idx] = a;
    d_Gf[idx] = a;
}

// ---------------- blocked fp32 Cholesky (lower), block = 64 ----------------
__global__ void chol_potf2(int kb) {
    int i = threadIdx.x;
    int off = kb * 64;
    __shared__ float s[64][65];
    for (int j = 0; j < 64; j++) s[i][j] = d_Gf[(off + i) * HH + off + j];
    __syncthreads();
    for (int j = 0; j < 64; j++) {
        if (i == j) s[j][j] = sqrtf(fmaxf(s[j][j], 1e-20f));
        __syncthreads();
        if (i > j) s[i][j] /= s[j][j];
        __syncthreads();
        if (i > j) {
            float lij = s[i][j];
            for (int k = j + 1; k <= i; k++) s[i][k] -= lij * s[k][j];
        }
        __syncthreads();
    }
    for (int j = 0; j <= i; j++) d_Gf[(off + i) * HH + off + j] = s[i][j];
    d_dinvf[off + i] = 1.0f / s[i][i];
}

__global__ __launch_bounds__(256) void chol_trsm(int kb) {
    int off = kb * 64;
    int base = off + 64;
    __shared__ float L[64][65];
    __shared__ float di[64];
    for (int i = threadIdx.x; i < 64 * 64; i += 256)
        L[i >> 6][i & 63] = d_Gf[(off + (i >> 6)) * HH + off + (i & 63)];
    if (threadIdx.x < 64) di[threadIdx.x] = d_dinvf[off + threadIdx.x];
    __syncthreads();
    int r = base + blockIdx.x * 256 + threadIdx.x;
    if (r >= HH) return;
    float* a = &d_Gf[r * HH + off];
    float x[64];
#pragma unroll
    for (int j = 0; j < 64; j++) x[j] = a[j];
#pragma unroll
    for (int j = 0; j < 64; j++) {
        float xj = x[j] * di[j];
        x[j] = xj;
#pragma unroll
        for (int tt = j + 1; tt < 64; tt++) x[tt] -= xj * L[tt][j];
    }
#pragma unroll
    for (int j = 0; j < 64; j++) a[j] = x[j];
}

__global__ __launch_bounds__(256) void chol_syrk(int kb) {
    int off = kb * 64;
    int base = off + 64;
    int i0 = base + blockIdx.y * 32;
    int j0 = base + blockIdx.x * 32;
    if (j0 > i0) return;
    __shared__ float Li[32][65];
    __shared__ float Lj[32][65];
    int tid = threadIdx.x;
    for (int i = tid; i < 32 * 64; i += 256) {
        int ii = i >> 6, t = i & 63;
        Li[ii][t] = d_Gf[(i0 + ii) * HH + off + t];
        Lj[ii][t] = d_Gf[(j0 + ii) * HH + off + t];
    }
    __syncthreads();
    int tx = tid & 31, ty = tid >> 5;
    float acc[4] = {0, 0, 0, 0};
    for (int t = 0; t < 64; t++) {
        float bj = Lj[tx][t];
#pragma unroll
        for (int r = 0; r < 4; r++) acc[r] += Li[(ty << 2) + r][t] * bj;
    }
#pragma unroll
    for (int r = 0; r < 4; r++) {
        int i = i0 + (ty << 2) + r;
        int j = j0 + tx;
        if (j <= i) d_Gf[i * HH + j] -= acc[r];
    }
}

// ---------------- triangular solves: L y = b ; L^T x = y (7 RHS); mode 0: wo=x, 1: wo+=x, b=res ----------------
__global__ __launch_bounds__(1024) void chol_solve(int mode) {
    int i = threadIdx.x;
    __shared__ float shy[64][CC];
    float y[CC];
    const float* b = (mode == 0) ? d_Qn : d_res;
#pragma unroll
    for (int c = 0; c < CC; c++) y[c] = b[i * CC + c];
    for (int jb = 0; jb < HH; jb += 64) {
        for (int j = jb; j < jb + 64; j++) {
            if (i == j) {
                float dgl = d_dinvf[j];
#pragma unroll
                for (int c = 0; c < CC; c++) { y[c] *= dgl; shy[j - jb][c] = y[c]; }
            }
            __syncthreads();
            if (i > j && i < jb + 64) {
                float lij = d_Gf[i * HH + j];
#pragma unroll
                for (int c = 0; c < CC; c++) y[c] -= lij * shy[j - jb][c];
            }
            __syncthreads();
        }
        if (i >= jb + 64) {
            for (int t = 0; t < 64; t++) {
                float lij = d_Gf[i * HH + jb + t];
#pragma unroll
                for (int c = 0; c < CC; c++) y[c] -= lij * shy[t][c];
            }
        }
        __syncthreads();
    }
    for (int jb = HH - 64; jb >= 0; jb -= 64) {
        for (int j = jb + 63; j >= jb; j--) {
            if (i == j) {
                float dgl = d_dinvf[j];
#pragma unroll
                for (int c = 0; c < CC; c++) { y[c] *= dgl; shy[j - jb][c] = y[c]; }
            }
            __syncthreads();
            if (i >= jb && i < j) {
                float lji = d_Gf[j * HH + i];
#pragma unroll
                for (int c = 0; c < CC; c++) y[c] -= lji * shy[j - jb][c];
            }
            __syncthreads();
        }
        if (i < jb) {
            for (int t = 0; t < 64; t++) {
                float lji = d_Gf[(jb + t) * HH + i];
#pragma unroll
                for (int c = 0; c < CC; c++) y[c] -= lji * shy[t][c];
            }
        }
        __syncthreads();
    }
    if (mode == 0) {
#pragma unroll
        for (int c = 0; c < CC; c++) d_wo[i * CC + c] = y[c];
    } else {
#pragma unroll
        for (int c = 0; c < CC; c++) d_wo[i * CC + c] += y[c];
    }
}

// ---------------- residual r = Qn - A*wo, fp32 TwoProd + Neumaier compensation ----------------
__global__ __launch_bounds__(256) void resid_kernel() {
    __shared__ float sw[HH * CC];
    int tid = threadIdx.x;
    for (int i = tid; i < HH * CC; i += 256) sw[i] = d_wo[i];
    __syncthreads();
    int wid = tid >> 5, lane = tid & 31;
    int row = blockIdx.x * 8 + wid;
    float s[CC], comp[CC];
#pragma unroll
    for (int c = 0; c < CC; c++) {
        s[c] = (lane == 0) ? d_Qn[row * CC + c] : 0.f;
        comp[c] = 0.f;
    }
    const float* arow = &d_GA[row * HH];
    for (int j = lane; j < HH; j += 32) {
        float na = -arow[j];
#pragma unroll
        for (int c = 0; c < CC; c++) {
            float w = sw[j * CC + c];
            float p = na * w;
            float e = fmaf(na, w, -p);
            float t = s[c] + p;
            float bb = t - s[c];
            float err = (s[c] - (t - bb)) + (p - bb);
            s[c] = t;
            comp[c] += err + e;
        }
    }
#pragma unroll
    for (int c = 0; c < CC; c++) {
#pragma unroll
        for (int off = 16; off > 0; off >>= 1) {
            float s2 = __shfl_xor_sync(0xffffffffu, s[c], off);
            float c2 = __shfl_xor_sync(0xffffffffu, comp[c], off);
            float t = s[c] + s2;
            float bb = t - s[c];
            float err = (s[c] - (t - bb)) + (s2 - bb);
            s[c] = t;
            comp[c] += c2 + err;
        }
    }
    if (lane == 0) {
#pragma unroll
        for (int c = 0; c < CC; c++) d_res[row * CC + c] = s[c] + comp[c];
    }
}

// ---------------- pred_domain = featH @ wo ----------------
__global__ __launch_bounds__(256) void final_kernel(float* __restrict__ out) {
    __shared__ float sw[HH * CC];
    int tid = threadIdx.x;
    for (int i = tid; i < HH * CC; i += 256) sw[i] = d_wo[i];
    __syncthreads();
    int warp = tid >> 5, lane = tid & 31;
    int n = blockIdx.x * 8 + warp;
    if (n >= NN) return;
    const float* a = &d_featH[(long long)n * HH];
    float acc[CC];
#pragma unroll
    for (int c = 0; c < CC; c++) acc[c] = 0.f;
    for (int h = lane; h < HH; h += 32) {
        float v = a[h];
#pragma unroll
        for (int c = 0; c < CC; c++) acc[c] += v * sw[h * CC + c];
    }
#pragma unroll
    for (int c = 0; c < CC; c++) {
#pragma unroll
        for (int off = 16; off > 0; off >>= 1)
            acc[c] += __shfl_xor_sync(0xffffffffu, acc[c], off);
    }
    if (lane == 0) {
#pragma unroll
        for (int c = 0; c < CC; c++) out[(long long)n * CC + c] = acc[c];
    }
}

// ---------------- launcher ----------------
extern "C" void kernel_launch(void* const* d_in, const int* in_sizes, int n_in,
                              void* d_out, int out_size) {
    const float* feat   = (const float*)d_in[0];
    const float* proto  = (const float*)d_in[1];
    const float* wrand  = (const float*)d_in[2];
    const float* Qin    = (const float*)d_in[3];
    const float* Gin    = (const float*)d_in[4];
    const float* coords = (const float*)d_in[5];
    const float* normz  = (const float*)d_in[6];
    const void*  nidx   = (const void*)d_in[7];
    float* out = (float*)d_out;

    cudaFuncSetAttribute(gram_hmma_kernel,
                         cudaFuncAttributeMaxDynamicSharedMemorySize, GS_TOTAL);

    preds_kernel<<<(NN + 255) / 256, 256>>>(feat, proto);                 // 0
    mask_kernel<<<(NN + 255) / 256, 256>>>(coords, normz, nidx);          // 1
    dummy_kernel<<<1, 32>>>();                                            // 2
    feath_kernel<<<dim3(HH / 64, KPAD / 64), 256>>>(feat, wrand);         // 3 <- ncu slot
    gram_hmma_kernel<<<dim3(NTRI, GSPLIT), 512, GS_TOTAL>>>();            // 4
    greduce_kernel<<<NTRI, 256>>>();
    qpart_kernel<<<dim3(HH / 256, NCHUNK), 256>>>();
    qreduce_kernel<<<(HH * CC + 255) / 256, 256>>>(Qin);
    convm_kernel<<<(HH * HH) / 256, 256>>>(Gin);

    for (int kb = 0; kb < HH / 64; kb++) {
        chol_potf2<<<1, 64>>>(kb);
        int rows = HH - (kb * 64 + 64);
        if (rows > 0) {
            chol_trsm<<<(rows + 255) / 256, 256>>>(kb);
            int nt = (rows + 31) / 32;
            chol_syrk<<<dim3(nt, nt), 256>>>(kb);
        }
    }
    chol_solve<<<1, 1024>>>(0);
    resid_kernel<<<HH / 8, 256>>>();
    chol_solve<<<1, 1024>>>(1);
    resid_kernel<<<HH / 8, 256>>>();
    chol_solve<<<1, 1024>>>(1);
    final_kernel<<<(NN + 7) / 8, 256>>>(out);
}